// round 4
// baseline (speedup 1.0000x reference)
#include <cuda_runtime.h>

// ---------------------------------------------------------------------------
// Problem constants (fixed by the reference)
// B=8, H=W=128, L=16384, DIM=256, C_ATTN=128, WS=8, SHIFT=4,
// HEADS=4, HD=32, HIDDEN=512, windows: 16x16=256, 64 tokens each.
//
// Scratch: single 512MB union buffer, slots of 33554432 floats (128MB).
//   S0: Q                (k_qkv .. k_grad)   then  y  (k_proj .. k_fc2)
//   S1: K                (k_qkv .. k_grad)   then  fc1 lower half
//   S2: V                (k_qkv .. k_attn)   then  fc1 upper half
//   S3: attn-out         (k_attn .. k_proj)  then  gate (k_dwgate .. k_fc2)
// fc1 occupies S1+S2 contiguously (67108864 floats).
// ---------------------------------------------------------------------------

#define SLOT 33554432
__device__ float g_scratch[4 * SLOT];
__device__ float g_qg[524288];      // [rest=(sb*128+c)][win]  (16*128*256)
__device__ float g_kg[524288];

#define PTR_Q    (g_scratch)
#define PTR_K    (g_scratch + SLOT)
#define PTR_V    (g_scratch + 2 * SLOT)
#define PTR_ATTN (g_scratch + 3 * SLOT)
#define PTR_Y    (g_scratch)
#define PTR_FC1  (g_scratch + SLOT)
#define PTR_GATE (g_scratch + 3 * SLOT)

// ---------------------------------------------------------------------------
// Kernel 1: LN1 + window partition (+roll for branch 1) + QKV GEMM.
// One block per (s, b, win): computes A (64 tok x 128 ch, normalized) and
// C = A @ qkv_w^T (64 x 384), scattered into Q/K/V in [sb][c][win][pos] layout.
// ---------------------------------------------------------------------------
__global__ __launch_bounds__(256) void k_qkv(
    const float* __restrict__ x, const float* __restrict__ n1g, const float* __restrict__ n1b,
    const float* __restrict__ qkv_w, const float* __restrict__ qkv_b)
{
    __shared__ float As[64][132];
    __shared__ float Ws[16][128];

    int blk = blockIdx.x;
    int win = blk & 255, sb = blk >> 8;
    int s = sb >> 3, b = sb & 7;
    int wy = win >> 4, wx = win & 15;
    int tid = threadIdx.x;

    // ---- Phase A: per-token LayerNorm (full 256 ch), keep branch 128 ch ----
    {
        int t = tid >> 2, q = tid & 3;          // 4 threads per token
        int py = t >> 3, px = t & 7;
        int hh = wy * 8 + py, ww = wx * 8 + px;
        if (s) { hh = (hh + 4) & 127; ww = (ww + 4) & 127; }
        const float* xrow = x + ((size_t)(b * 16384 + hh * 128 + ww)) * 256;
        const float4* xr4 = (const float4*)xrow + q * 16;
        float sum = 0.f, sq = 0.f;
        #pragma unroll
        for (int i = 0; i < 16; i++) {
            float4 v = xr4[i];
            sum += v.x + v.y + v.z + v.w;
            sq  += v.x * v.x + v.y * v.y + v.z * v.z + v.w * v.w;
        }
        sum += __shfl_xor_sync(0xffffffffu, sum, 1);
        sum += __shfl_xor_sync(0xffffffffu, sum, 2);
        sq  += __shfl_xor_sync(0xffffffffu, sq, 1);
        sq  += __shfl_xor_sync(0xffffffffu, sq, 2);
        float mean = sum * (1.f / 256.f);
        float rstd = rsqrtf(sq * (1.f / 256.f) - mean * mean + 1e-5f);

        const float4* xb = (const float4*)(xrow + s * 128 + q * 32);
        const float4* gg = (const float4*)(n1g + s * 128 + q * 32);
        const float4* bb = (const float4*)(n1b + s * 128 + q * 32);
        #pragma unroll
        for (int i = 0; i < 8; i++) {
            float4 v = xb[i], gv = gg[i], bv = bb[i];
            int c = q * 32 + i * 4;
            As[t][c + 0] = (v.x - mean) * rstd * gv.x + bv.x;
            As[t][c + 1] = (v.y - mean) * rstd * gv.y + bv.y;
            As[t][c + 2] = (v.z - mean) * rstd * gv.z + bv.z;
            As[t][c + 3] = (v.w - mean) * rstd * gv.w + bv.w;
        }
    }
    __syncthreads();

    // ---- Phase B: GEMM, 3 chunks of 128 output cols (q, k, v) ----
    int ty = tid >> 4, tx = tid & 15;
    int t0 = ty * 4, r0 = tx * 8;
    int lr = tid >> 1, lk = (tid & 1) * 8;

    for (int chunk = 0; chunk < 3; chunk++) {
        float acc[4][8];
        #pragma unroll
        for (int i = 0; i < 4; i++)
            #pragma unroll
            for (int j = 0; j < 8; j++) acc[i][j] = 0.f;

        for (int k0 = 0; k0 < 128; k0 += 16) {
            const float4* wsrc = (const float4*)(qkv_w + (size_t)(chunk * 128 + lr) * 128 + k0 + lk);
            float4 w0 = wsrc[0], w1 = wsrc[1];
            __syncthreads();
            Ws[lk + 0][lr] = w0.x; Ws[lk + 1][lr] = w0.y; Ws[lk + 2][lr] = w0.z; Ws[lk + 3][lr] = w0.w;
            Ws[lk + 4][lr] = w1.x; Ws[lk + 5][lr] = w1.y; Ws[lk + 6][lr] = w1.z; Ws[lk + 7][lr] = w1.w;
            __syncthreads();
            #pragma unroll
            for (int kk = 0; kk < 16; kk++) {
                float a0 = As[t0 + 0][k0 + kk];
                float a1 = As[t0 + 1][k0 + kk];
                float a2 = As[t0 + 2][k0 + kk];
                float a3 = As[t0 + 3][k0 + kk];
                float4 b0 = *(const float4*)&Ws[kk][r0];
                float4 b1 = *(const float4*)&Ws[kk][r0 + 4];
                acc[0][0] += a0 * b0.x; acc[0][1] += a0 * b0.y; acc[0][2] += a0 * b0.z; acc[0][3] += a0 * b0.w;
                acc[0][4] += a0 * b1.x; acc[0][5] += a0 * b1.y; acc[0][6] += a0 * b1.z; acc[0][7] += a0 * b1.w;
                acc[1][0] += a1 * b0.x; acc[1][1] += a1 * b0.y; acc[1][2] += a1 * b0.z; acc[1][3] += a1 * b0.w;
                acc[1][4] += a1 * b1.x; acc[1][5] += a1 * b1.y; acc[1][6] += a1 * b1.z; acc[1][7] += a1 * b1.w;
                acc[2][0] += a2 * b0.x; acc[2][1] += a2 * b0.y; acc[2][2] += a2 * b0.z; acc[2][3] += a2 * b0.w;
                acc[2][4] += a2 * b1.x; acc[2][5] += a2 * b1.y; acc[2][6] += a2 * b1.z; acc[2][7] += a2 * b1.w;
                acc[3][0] += a3 * b0.x; acc[3][1] += a3 * b0.y; acc[3][2] += a3 * b0.z; acc[3][3] += a3 * b0.w;
                acc[3][4] += a3 * b1.x; acc[3][5] += a3 * b1.y; acc[3][6] += a3 * b1.z; acc[3][7] += a3 * b1.w;
            }
        }
        float* dst = (chunk == 0) ? PTR_Q : (chunk == 1) ? PTR_K : PTR_V;
        #pragma unroll
        for (int j = 0; j < 8; j++) {
            int r = r0 + j;
            float bias = qkv_b[chunk * 128 + r];
            float4 o = make_float4(acc[0][j] + bias, acc[1][j] + bias, acc[2][j] + bias, acc[3][j] + bias);
            *(float4*)&dst[((size_t)(sb * 128 + r) * 256 + win) * 64 + t0] = o;
        }
    }
}

// ---------------------------------------------------------------------------
// Kernel 2: finite-difference gradient scores. One thread per (sb,c,win).
// 524288 items total -> grid (2048, 2). blockIdx.y: 0 -> Q (scaled), 1 -> K.
// ---------------------------------------------------------------------------
__global__ __launch_bounds__(256) void k_grad()
{
    int idx = blockIdx.x * 256 + threadIdx.x;     // 0 .. 524287
    const float* src = blockIdx.y ? PTR_K : PTR_Q;
    float*       dst = blockIdx.y ? g_kg : g_qg;
    float scale = blockIdx.y ? 1.f : 0.17677669529663687f;  // hd^-0.5

    float v[64];
    const float4* p = (const float4*)(src + (size_t)idx * 64);
    #pragma unroll
    for (int i = 0; i < 16; i++) {
        float4 t = p[i];
        v[i * 4 + 0] = t.x; v[i * 4 + 1] = t.y; v[i * 4 + 2] = t.z; v[i * 4 + 3] = t.w;
    }
    float sc = 0.f;
    #pragma unroll
    for (int py = 0; py < 8; py++)
        #pragma unroll
        for (int px = 0; px < 8; px++) {
            float t = v[py * 8 + px];
            float gx = px ? (t - v[py * 8 + px - 1]) : t;
            float gy = py ? (t - v[(py - 1) * 8 + px]) : t;
            sc += fabsf(gx) + fabsf(gy);
        }
    dst[idx] = sc * scale;
}

// ---------------------------------------------------------------------------
// Kernel 3: inter-window rank-1 softmax attention.
// One block per (s,b,h,d) = "rest"; thread i handles destination window i.
// out[i][t] = sum_j softmax_j(qg_i * kg_j) * V[j][t]
// ---------------------------------------------------------------------------
__global__ __launch_bounds__(256) void k_attn()
{
    __shared__ float kg_s[256];
    __shared__ float Vs[64 * 64];
    __shared__ float smin[8], smax[8];

    int rest = blockIdx.x;     // 0..2047
    int i = threadIdx.x;

    kg_s[i] = g_kg[(size_t)rest * 256 + i];
    float kmin = kg_s[i], kmax = kmin;
    #pragma unroll
    for (int o = 16; o; o >>= 1) {
        kmin = fminf(kmin, __shfl_xor_sync(0xffffffffu, kmin, o));
        kmax = fmaxf(kmax, __shfl_xor_sync(0xffffffffu, kmax, o));
    }
    if ((i & 31) == 0) { smin[i >> 5] = kmin; smax[i >> 5] = kmax; }
    __syncthreads();
    kmin = smin[0]; kmax = smax[0];
    #pragma unroll
    for (int w = 1; w < 8; w++) { kmin = fminf(kmin, smin[w]); kmax = fmaxf(kmax, smax[w]); }

    float qgi = g_qg[(size_t)rest * 256 + i];
    float m = (qgi >= 0.f) ? qgi * kmax : qgi * kmin;   // exact row max

    float acc[64];
    #pragma unroll
    for (int t = 0; t < 64; t++) acc[t] = 0.f;
    float Z = 0.f;

    const float* Vbase = PTR_V;
    for (int jc = 0; jc < 4; jc++) {
        __syncthreads();
        const float4* vsrc = (const float4*)(Vbase + ((size_t)rest * 256 + jc * 64) * 64);
        float4* vdst = (float4*)Vs;
        #pragma unroll
        for (int u = 0; u < 4; u++) vdst[i + u * 256] = vsrc[i + u * 256];
        __syncthreads();
        #pragma unroll 2
        for (int j = 0; j < 64; j++) {
            float e = __expf(qgi * kg_s[jc * 64 + j] - m);
            Z += e;
            const float4* vr = (const float4*)(Vs + j * 64);
            #pragma unroll
            for (int t = 0; t < 16; t++) {
                float4 vv = vr[t];
                acc[t * 4 + 0] += e * vv.x;
                acc[t * 4 + 1] += e * vv.y;
                acc[t * 4 + 2] += e * vv.z;
                acc[t * 4 + 3] += e * vv.w;
            }
        }
    }
    float inv = 1.f / Z;
    float4* od = (float4*)(PTR_ATTN + ((size_t)rest * 256 + i) * 64);
    #pragma unroll
    for (int t = 0; t < 16; t++)
        od[t] = make_float4(acc[t * 4] * inv, acc[t * 4 + 1] * inv,
                            acc[t * 4 + 2] * inv, acc[t * 4 + 3] * inv);
}

// ---------------------------------------------------------------------------
// Kernel 4: proj GEMM + window-reverse (+roll back for branch 1) + residual.
// One block per (s,b,win). Writes y = x + attn_out into PTR_Y (B,L,256).
// NOTE: PTR_Y aliases PTR_Q (dead after k_grad) — safe.
// ---------------------------------------------------------------------------
__global__ __launch_bounds__(256) void k_proj(
    const float* __restrict__ x, const float* __restrict__ proj_w, const float* __restrict__ proj_b)
{
    __shared__ float As[64][132];
    __shared__ float Ws[16][128];

    int blk = blockIdx.x;
    int win = blk & 255, sb = blk >> 8;
    int s = sb >> 3, b = sb & 7;
    int wy = win >> 4, wx = win & 15;
    int tid = threadIdx.x;

    // gather A: As[pos][c] from attn[sb*128+c][win][pos]
    {
        int c = tid >> 1, half = tid & 1;
        const float4* src = (const float4*)(PTR_ATTN + ((size_t)(sb * 128 + c) * 256 + win) * 64 + half * 32);
        #pragma unroll
        for (int u = 0; u < 8; u++) {
            float4 v = src[u];
            int p = half * 32 + u * 4;
            As[p + 0][c] = v.x; As[p + 1][c] = v.y; As[p + 2][c] = v.z; As[p + 3][c] = v.w;
        }
    }
    __syncthreads();

    int ty = tid >> 4, tx = tid & 15;
    int t0 = ty * 4, r0 = tx * 8;
    int lr = tid >> 1, lk = (tid & 1) * 8;

    float acc[4][8];
    #pragma unroll
    for (int i = 0; i < 4; i++)
        #pragma unroll
        for (int j = 0; j < 8; j++) acc[i][j] = 0.f;

    for (int k0 = 0; k0 < 128; k0 += 16) {
        const float4* wsrc = (const float4*)(proj_w + (size_t)lr * 128 + k0 + lk);
        float4 w0 = wsrc[0], w1 = wsrc[1];
        __syncthreads();
        Ws[lk + 0][lr] = w0.x; Ws[lk + 1][lr] = w0.y; Ws[lk + 2][lr] = w0.z; Ws[lk + 3][lr] = w0.w;
        Ws[lk + 4][lr] = w1.x; Ws[lk + 5][lr] = w1.y; Ws[lk + 6][lr] = w1.z; Ws[lk + 7][lr] = w1.w;
        __syncthreads();
        #pragma unroll
        for (int kk = 0; kk < 16; kk++) {
            float a0 = As[t0 + 0][k0 + kk];
            float a1 = As[t0 + 1][k0 + kk];
            float a2 = As[t0 + 2][k0 + kk];
            float a3 = As[t0 + 3][k0 + kk];
            float4 b0 = *(const float4*)&Ws[kk][r0];
            float4 b1 = *(const float4*)&Ws[kk][r0 + 4];
            acc[0][0] += a0 * b0.x; acc[0][1] += a0 * b0.y; acc[0][2] += a0 * b0.z; acc[0][3] += a0 * b0.w;
            acc[0][4] += a0 * b1.x; acc[0][5] += a0 * b1.y; acc[0][6] += a0 * b1.z; acc[0][7] += a0 * b1.w;
            acc[1][0] += a1 * b0.x; acc[1][1] += a1 * b0.y; acc[1][2] += a1 * b0.z; acc[1][3] += a1 * b0.w;
            acc[1][4] += a1 * b1.x; acc[1][5] += a1 * b1.y; acc[1][6] += a1 * b1.z; acc[1][7] += a1 * b1.w;
            acc[2][0] += a2 * b0.x; acc[2][1] += a2 * b0.y; acc[2][2] += a2 * b0.z; acc[2][3] += a2 * b0.w;
            acc[2][4] += a2 * b1.x; acc[2][5] += a2 * b1.y; acc[2][6] += a2 * b1.z; acc[2][7] += a2 * b1.w;
            acc[3][0] += a3 * b0.x; acc[3][1] += a3 * b0.y; acc[3][2] += a3 * b0.z; acc[3][3] += a3 * b0.w;
            acc[3][4] += a3 * b1.x; acc[3][5] += a3 * b1.y; acc[3][6] += a3 * b1.z; acc[3][7] += a3 * b1.w;
        }
    }

    float b0b = proj_b[r0 + 0], b1b = proj_b[r0 + 1], b2b = proj_b[r0 + 2], b3b = proj_b[r0 + 3];
    float b4b = proj_b[r0 + 4], b5b = proj_b[r0 + 5], b6b = proj_b[r0 + 6], b7b = proj_b[r0 + 7];
    #pragma unroll
    for (int ii = 0; ii < 4; ii++) {
        int t = t0 + ii;
        int py = t >> 3, px = t & 7;
        int hh = wy * 8 + py, ww = wx * 8 + px;
        if (s) { hh = (hh + 4) & 127; ww = (ww + 4) & 127; }
        size_t base = ((size_t)(b * 16384 + hh * 128 + ww)) * 256 + s * 128 + r0;
        float4 x0 = *(const float4*)(x + base);
        float4 x1 = *(const float4*)(x + base + 4);
        float4 o0 = make_float4(acc[ii][0] + b0b + x0.x, acc[ii][1] + b1b + x0.y,
                                acc[ii][2] + b2b + x0.z, acc[ii][3] + b3b + x0.w);
        float4 o1 = make_float4(acc[ii][4] + b4b + x1.x, acc[ii][5] + b5b + x1.y,
                                acc[ii][6] + b6b + x1.z, acc[ii][7] + b7b + x1.w);
        *(float4*)(PTR_Y + base) = o0;
        *(float4*)(PTR_Y + base + 4) = o1;
    }
}

// ---------------------------------------------------------------------------
// Kernel 5: LN2 + fc1 (256 -> 512). Block: 64 tokens x 128 out cols.
// Output written NCHW into PTR_FC1 (aliases K+V slots, dead) for the dw conv.
// ---------------------------------------------------------------------------
__global__ __launch_bounds__(256) void k_fc1(
    const float* __restrict__ n2g, const float* __restrict__ n2b,
    const float* __restrict__ fc1_w, const float* __restrict__ fc1_b)
{
    __shared__ float As[64][33];
    __shared__ float Ws[32][128];
    __shared__ float mu_s[64], rs_s[64];

    int tok0 = blockIdx.x * 64;
    int r0g = blockIdx.y * 128;
    int b = tok0 >> 14;
    int hw0 = tok0 & 16383;
    int tid = threadIdx.x;

    // per-row LN stats
    {
        int t = tid >> 2, q = tid & 3;
        const float4* yr = (const float4*)(PTR_Y + (size_t)(tok0 + t) * 256) + q * 16;
        float sum = 0.f, sq = 0.f;
        #pragma unroll
        for (int i = 0; i < 16; i++) {
            float4 v = yr[i];
            sum += v.x + v.y + v.z + v.w;
            sq  += v.x * v.x + v.y * v.y + v.z * v.z + v.w * v.w;
        }
        sum += __shfl_xor_sync(0xffffffffu, sum, 1);
        sum += __shfl_xor_sync(0xffffffffu, sum, 2);
        sq  += __shfl_xor_sync(0xffffffffu, sq, 1);
        sq  += __shfl_xor_sync(0xffffffffu, sq, 2);
        float mean = sum * (1.f / 256.f);
        float rstd = rsqrtf(sq * (1.f / 256.f) - mean * mean + 1e-5f);
        if (q == 0) { mu_s[t] = mean; rs_s[t] = rstd; }
    }
    __syncthreads();

    int ty = tid >> 4, tx = tid & 15;
    int t0 = ty * 4, r0 = tx * 8;
    int at = tid >> 2, aq = tid & 3;
    int lr = tid >> 1, lk = (tid & 1) * 16;

    float acc[4][8];
    #pragma unroll
    for (int i = 0; i < 4; i++)
        #pragma unroll
        for (int j = 0; j < 8; j++) acc[i][j] = 0.f;

    for (int k0 = 0; k0 < 256; k0 += 32) {
        // A-tile (normalized) regs
        float mu = mu_s[at], rs = rs_s[at];
        const float4* yr = (const float4*)(PTR_Y + (size_t)(tok0 + at) * 256 + k0 + aq * 8);
        float4 v0 = yr[0], v1 = yr[1];
        const float4* gg = (const float4*)(n2g + k0 + aq * 8);
        float4 ga = gg[0], gb = gg[1];
        const float4* bv = (const float4*)(n2b + k0 + aq * 8);
        float4 ba = bv[0], bb = bv[1];
        // W-tile regs
        const float4* wsrc = (const float4*)(fc1_w + (size_t)(r0g + lr) * 256 + k0 + lk);
        float4 w0 = wsrc[0], w1 = wsrc[1], w2 = wsrc[2], w3 = wsrc[3];
        __syncthreads();
        {
            int c = aq * 8;
            As[at][c + 0] = (v0.x - mu) * rs * ga.x + ba.x;
            As[at][c + 1] = (v0.y - mu) * rs * ga.y + ba.y;
            As[at][c + 2] = (v0.z - mu) * rs * ga.z + ba.z;
            As[at][c + 3] = (v0.w - mu) * rs * ga.w + ba.w;
            As[at][c + 4] = (v1.x - mu) * rs * gb.x + bb.x;
            As[at][c + 5] = (v1.y - mu) * rs * gb.y + bb.y;
            As[at][c + 6] = (v1.z - mu) * rs * gb.z + bb.z;
            As[at][c + 7] = (v1.w - mu) * rs * gb.w + bb.w;
        }
        Ws[lk +  0][lr] = w0.x; Ws[lk +  1][lr] = w0.y; Ws[lk +  2][lr] = w0.z; Ws[lk +  3][lr] = w0.w;
        Ws[lk +  4][lr] = w1.x; Ws[lk +  5][lr] = w1.y; Ws[lk +  6][lr] = w1.z; Ws[lk +  7][lr] = w1.w;
        Ws[lk +  8][lr] = w2.x; Ws[lk +  9][lr] = w2.y; Ws[lk + 10][lr] = w2.z; Ws[lk + 11][lr] = w2.w;
        Ws[lk + 12][lr] = w3.x; Ws[lk + 13][lr] = w3.y; Ws[lk + 14][lr] = w3.z; Ws[lk + 15][lr] = w3.w;
        __syncthreads();
        #pragma unroll
        for (int kk = 0; kk < 32; kk++) {
            float a0 = As[t0 + 0][kk];
            float a1 = As[t0 + 1][kk];
            float a2 = As[t0 + 2][kk];
            float a3 = As[t0 + 3][kk];
            float4 b0 = *(const float4*)&Ws[kk][r0];
            float4 b1 = *(const float4*)&Ws[kk][r0 + 4];
            acc[0][0] += a0 * b0.x; acc[0][1] += a0 * b0.y; acc[0][2] += a0 * b0.z; acc[0][3] += a0 * b0.w;
            acc[0][4] += a0 * b1.x; acc[0][5] += a0 * b1.y; acc[0][6] += a0 * b1.z; acc[0][7] += a0 * b1.w;
            acc[1][0] += a1 * b0.x; acc[1][1] += a1 * b0.y; acc[1][2] += a1 * b0.z; acc[1][3] += a1 * b0.w;
            acc[1][4] += a1 * b1.x; acc[1][5] += a1 * b1.y; acc[1][6] += a1 * b1.z; acc[1][7] += a1 * b1.w;
            acc[2][0] += a2 * b0.x; acc[2][1] += a2 * b0.y; acc[2][2] += a2 * b0.z; acc[2][3] += a2 * b0.w;
            acc[2][4] += a2 * b1.x; acc[2][5] += a2 * b1.y; acc[2][6] += a2 * b1.z; acc[2][7] += a2 * b1.w;
            acc[3][0] += a3 * b0.x; acc[3][1] += a3 * b0.y; acc[3][2] += a3 * b0.z; acc[3][3] += a3 * b0.w;
            acc[3][4] += a3 * b1.x; acc[3][5] += a3 * b1.y; acc[3][6] += a3 * b1.z; acc[3][7] += a3 * b1.w;
        }
    }
    #pragma unroll
    for (int j = 0; j < 8; j++) {
        int r = r0 + j;
        float bias = fc1_b[r0g + r];
        float4 o = make_float4(acc[0][j] + bias, acc[1][j] + bias, acc[2][j] + bias, acc[3][j] + bias);
        *(float4*)&PTR_FC1[(size_t)(b * 512 + r0g + r) * 16384 + hw0 + t0] = o;
    }
}

// ---------------------------------------------------------------------------
// Kernel 6: depthwise 3x3 conv (pad 1) + gating x1*x2, NCHW in/out.
// Block: (row-tile of 4 rows, channel-pair c, batch).
// ---------------------------------------------------------------------------
__global__ __launch_bounds__(256) void k_dwgate(
    const float* __restrict__ dw_w, const float* __restrict__ dw_b)
{
    __shared__ float in0[6][130];
    __shared__ float in1[6][130];
    __shared__ float wsm[2][9];
    __shared__ float bsm[2];

    int y0 = blockIdx.x * 4;
    int c  = blockIdx.y;
    int b  = blockIdx.z;
    int tid = threadIdx.x;

    if (tid < 18) { int ch = tid / 9, k = tid - ch * 9; wsm[ch][k] = dw_w[(size_t)(c + ch * 256) * 9 + k]; }
    if (tid < 2) bsm[tid] = dw_b[c + tid * 256];

    for (int e = tid; e < 2 * 6 * 130; e += 256) {
        int ch = e / 780;
        int rem = e - ch * 780;
        int rr = rem / 130;
        int cc = rem - rr * 130;
        int gy = y0 - 1 + rr, gx = cc - 1;
        float v = 0.f;
        if (gy >= 0 && gy < 128 && gx >= 0 && gx < 128)
            v = PTR_FC1[(size_t)(b * 512 + c + ch * 256) * 16384 + gy * 128 + gx];
        if (ch) in1[rr][cc] = v; else in0[rr][cc] = v;
    }
    __syncthreads();

    #pragma unroll
    for (int k = 0; k < 2; k++) {
        int o = tid + k * 256;          // 0..511
        int yy = o >> 7, xx = o & 127;
        float c0 = bsm[0], c1 = bsm[1];
        #pragma unroll
        for (int ky = 0; ky < 3; ky++)
            #pragma unroll
            for (int kx = 0; kx < 3; kx++) {
                c0 += wsm[0][ky * 3 + kx] * in0[yy + ky][xx + kx];
                c1 += wsm[1][ky * 3 + kx] * in1[yy + ky][xx + kx];
            }
        PTR_GATE[(size_t)(b * 256 + c) * 16384 + (y0 + yy) * 128 + xx] = c0 * c1;
    }
}

// ---------------------------------------------------------------------------
// Kernel 7: fc2 (256 -> 256) + residual add -> d_out.
// ---------------------------------------------------------------------------
__global__ __launch_bounds__(256) void k_fc2(
    const float* __restrict__ fc2_w, const float* __restrict__ fc2_b, float* __restrict__ out)
{
    __shared__ float As[64][33];
    __shared__ float Ws[32][128];

    int tok0 = blockIdx.x * 64;
    int r0g = blockIdx.y * 128;
    int b = tok0 >> 14;
    int hw0 = tok0 & 16383;
    int tid = threadIdx.x;

    int ty = tid >> 4, tx = tid & 15;
    int t0 = ty * 4, r0 = tx * 8;
    int akk = tid >> 3, at8 = (tid & 7) * 8;
    int lr = tid >> 1, lk = (tid & 1) * 16;

    float acc[4][8];
    #pragma unroll
    for (int i = 0; i < 4; i++)
        #pragma unroll
        for (int j = 0; j < 8; j++) acc[i][j] = 0.f;

    for (int k0 = 0; k0 < 256; k0 += 32) {
        const float4* asrc = (const float4*)(PTR_GATE + (size_t)(b * 256 + k0 + akk) * 16384 + hw0 + at8);
        float4 a0 = asrc[0], a1 = asrc[1];
        const float4* wsrc = (const float4*)(fc2_w + (size_t)(r0g + lr) * 256 + k0 + lk);
        float4 w0 = wsrc[0], w1 = wsrc[1], w2 = wsrc[2], w3 = wsrc[3];
        __syncthreads();
        As[at8 + 0][akk] = a0.x; As[at8 + 1][akk] = a0.y; As[at8 + 2][akk] = a0.z; As[at8 + 3][akk] = a0.w;
        As[at8 + 4][akk] = a1.x; As[at8 + 5][akk] = a1.y; As[at8 + 6][akk] = a1.z; As[at8 + 7][akk] = a1.w;
        Ws[lk +  0][lr] = w0.x; Ws[lk +  1][lr] = w0.y; Ws[lk +  2][lr] = w0.z; Ws[lk +  3][lr] = w0.w;
        Ws[lk +  4][lr] = w1.x; Ws[lk +  5][lr] = w1.y; Ws[lk +  6][lr] = w1.z; Ws[lk +  7][lr] = w1.w;
        Ws[lk +  8][lr] = w2.x; Ws[lk +  9][lr] = w2.y; Ws[lk + 10][lr] = w2.z; Ws[lk + 11][lr] = w2.w;
        Ws[lk + 12][lr] = w3.x; Ws[lk + 13][lr] = w3.y; Ws[lk + 14][lr] = w3.z; Ws[lk + 15][lr] = w3.w;
        __syncthreads();
        #pragma unroll
        for (int kk = 0; kk < 32; kk++) {
            float a0v = As[t0 + 0][kk];
            float a1v = As[t0 + 1][kk];
            float a2v = As[t0 + 2][kk];
            float a3v = As[t0 + 3][kk];
            float4 b0 = *(const float4*)&Ws[kk][r0];
            float4 b1 = *(const float4*)&Ws[kk][r0 + 4];
            acc[0][0] += a0v * b0.x; acc[0][1] += a0v * b0.y; acc[0][2] += a0v * b0.z; acc[0][3] += a0v * b0.w;
            acc[0][4] += a0v * b1.x; acc[0][5] += a0v * b1.y; acc[0][6] += a0v * b1.z; acc[0][7] += a0v * b1.w;
            acc[1][0] += a1v * b0.x; acc[1][1] += a1v * b0.y; acc[1][2] += a1v * b0.z; acc[1][3] += a1v * b0.w;
            acc[1][4] += a1v * b1.x; acc[1][5] += a1v * b1.y; acc[1][6] += a1v * b1.z; acc[1][7] += a1v * b1.w;
            acc[2][0] += a2v * b0.x; acc[2][1] += a2v * b0.y; acc[2][2] += a2v * b0.z; acc[2][3] += a2v * b0.w;
            acc[2][4] += a2v * b1.x; acc[2][5] += a2v * b1.y; acc[2][6] += a2v * b1.z; acc[2][7] += a2v * b1.w;
            acc[3][0] += a3v * b0.x; acc[3][1] += a3v * b0.y; acc[3][2] += a3v * b0.z; acc[3][3] += a3v * b0.w;
            acc[3][4] += a3v * b1.x; acc[3][5] += a3v * b1.y; acc[3][6] += a3v * b1.z; acc[3][7] += a3v * b1.w;
        }
    }

    #pragma unroll
    for (int ii = 0; ii < 4; ii++) {
        size_t base = (size_t)(tok0 + t0 + ii) * 256 + r0g + r0;
        float4 y0v = *(const float4*)(PTR_Y + base);
        float4 y1v = *(const float4*)(PTR_Y + base + 4);
        float4 o0 = make_float4(acc[ii][0] + fc2_b[r0g + r0 + 0] + y0v.x,
                                acc[ii][1] + fc2_b[r0g + r0 + 1] + y0v.y,
                                acc[ii][2] + fc2_b[r0g + r0 + 2] + y0v.z,
                                acc[ii][3] + fc2_b[r0g + r0 + 3] + y0v.w);
        float4 o1 = make_float4(acc[ii][4] + fc2_b[r0g + r0 + 4] + y1v.x,
                                acc[ii][5] + fc2_b[r0g + r0 + 5] + y1v.y,
                                acc[ii][6] + fc2_b[r0g + r0 + 6] + y1v.z,
                                acc[ii][7] + fc2_b[r0g + r0 + 7] + y1v.w);
        *(float4*)(out + base) = o0;
        *(float4*)(out + base + 4) = o1;
    }
}

// ---------------------------------------------------------------------------
extern "C" void kernel_launch(void* const* d_in, const int* in_sizes, int n_in,
                              void* d_out, int out_size)
{
    const float* x      = (const float*)d_in[0];
    const float* n1g    = (const float*)d_in[1];
    const float* n1b    = (const float*)d_in[2];
    const float* qkv_w  = (const float*)d_in[3];
    const float* qkv_b  = (const float*)d_in[4];
    const float* proj_w = (const float*)d_in[5];
    const float* proj_b = (const float*)d_in[6];
    const float* n2g    = (const float*)d_in[7];
    const float* n2b    = (const float*)d_in[8];
    const float* fc1_w  = (const float*)d_in[9];
    const float* fc1_b  = (const float*)d_in[10];
    const float* dw_w   = (const float*)d_in[11];
    const float* dw_b   = (const float*)d_in[12];
    const float* fc2_w  = (const float*)d_in[13];
    const float* fc2_b  = (const float*)d_in[14];
    float* out = (float*)d_out;

    k_qkv<<<4096, 256>>>(x, n1g, n1b, qkv_w, qkv_b);
    k_grad<<<dim3(2048, 2), 256>>>();
    k_attn<<<2048, 256>>>();
    k_proj<<<4096, 256>>>(x, proj_w, proj_b);
    k_fc1<<<dim3(2048, 4), 256>>>(n2g, n2b, fc1_w, fc1_b);
    k_dwgate<<<dim3(32, 256, 8), 256>>>(dw_w, dw_b);
    k_fc2<<<dim3(2048, 2), 256>>>(fc2_w, fc2_b, out);
}

// round 6
// speedup vs baseline: 1.3860x; 1.3860x over previous
#include <cuda_runtime.h>
#include <cuda_bf16.h>
#include <cstdint>

// ---------------------------------------------------------------------------
// B=8, H=W=128, L=16384, DIM=256, C_ATTN=128, WS=8, SHIFT=4,
// HEADS=4, HD=32, HIDDEN=512, 256 windows x 64 tokens, 2 shift branches.
//
// Scratch slots (128MB each):
//   S0: Q  -> y (residual, live to end)
//   S1: K  -> fc1 out (lower)  -> gate_t bf16 (after dwgate)
//   S2: V  -> fc1 out (upper)
//   S3: attn-out -> Yn bf16 (ln2 out) -> gate fp32 NCHW (dwgate out)
// ---------------------------------------------------------------------------

#define SLOT 33554432
__device__ float g_scratch[4 * SLOT];
__device__ float g_qg[524288];
__device__ float g_kg[524288];
__device__ __nv_bfloat16 g_w1b[512 * 256];
__device__ __nv_bfloat16 g_w2b[256 * 256];

#define PTR_Q    (g_scratch)
#define PTR_K    (g_scratch + SLOT)
#define PTR_V    (g_scratch + 2 * SLOT)
#define PTR_ATTN (g_scratch + 3 * SLOT)
#define PTR_Y    (g_scratch)
#define PTR_FC1  (g_scratch + SLOT)
#define PTR_GATE (g_scratch + 3 * SLOT)
#define PTR_YN   ((__nv_bfloat16*)(g_scratch + 3 * SLOT))
#define PTR_GT   ((__nv_bfloat16*)(g_scratch + SLOT))

// ------------------------------ helpers ------------------------------------
__device__ __forceinline__ uint32_t smem_u32(const void* p) {
    uint32_t a;
    asm("{ .reg .u64 t; cvta.to.shared.u64 t, %1; cvt.u32.u64 %0, t; }" : "=r"(a) : "l"(p));
    return a;
}
__device__ __forceinline__ void ldmx4(uint32_t* r, uint32_t addr) {
    asm volatile("ldmatrix.sync.aligned.m8n8.x4.shared.b16 {%0,%1,%2,%3}, [%4];"
        : "=r"(r[0]), "=r"(r[1]), "=r"(r[2]), "=r"(r[3]) : "r"(addr));
}
__device__ __forceinline__ void mma16816(float* c, const uint32_t* a, uint32_t b0, uint32_t b1) {
    asm volatile("mma.sync.aligned.m16n8k16.row.col.f32.bf16.bf16.f32 "
        "{%0,%1,%2,%3}, {%4,%5,%6,%7}, {%8,%9}, {%0,%1,%2,%3};"
        : "+f"(c[0]), "+f"(c[1]), "+f"(c[2]), "+f"(c[3])
        : "r"(a[0]), "r"(a[1]), "r"(a[2]), "r"(a[3]), "r"(b0), "r"(b1));
}

// 128x128 (K=256) bf16 mma core. smem tiles row-major with 264-elem stride.
// Warp grid 4x2: warp (wm, wn) owns rows [wm*32,+32) x cols [wn*64,+64).
#define TSTRIDE 264
#define TSTRB   (TSTRIDE * 2)

__device__ __forceinline__ void mma_tile_128(
    uint32_t sA, uint32_t sB, int lane, int wm, int wn, float (&c)[2][8][4])
{
    uint32_t aRowB = sA + (uint32_t)(wm * 32 + (lane & 15)) * TSTRB + (uint32_t)((lane >> 4) << 4);
    uint32_t bRowB = sB + (uint32_t)(wn * 64 + (lane & 7) + ((lane >> 4) << 3)) * TSTRB
                   + (uint32_t)(((lane >> 3) & 1) << 4);
    #pragma unroll
    for (int k0 = 0; k0 < 256; k0 += 16) {
        uint32_t a[2][4];
        #pragma unroll
        for (int mi = 0; mi < 2; mi++)
            ldmx4(a[mi], aRowB + (uint32_t)(mi * 16) * TSTRB + k0 * 2);
        uint32_t bf[4][4];
        #pragma unroll
        for (int nf = 0; nf < 4; nf++)
            ldmx4(bf[nf], bRowB + (uint32_t)(nf * 16) * TSTRB + k0 * 2);
        #pragma unroll
        for (int mi = 0; mi < 2; mi++)
            #pragma unroll
            for (int n8 = 0; n8 < 8; n8++)
                mma16816(c[mi][n8], a[mi], bf[n8 >> 1][(n8 & 1) * 2], bf[n8 >> 1][(n8 & 1) * 2 + 1]);
    }
}

// ---------------------------------------------------------------------------
// Kernel 1: LN1 + window partition (+roll) + QKV GEMM (fp32 SIMT).
// ---------------------------------------------------------------------------
__global__ __launch_bounds__(256) void k_qkv(
    const float* __restrict__ x, const float* __restrict__ n1g, const float* __restrict__ n1b,
    const float* __restrict__ qkv_w, const float* __restrict__ qkv_b)
{
    __shared__ float As[64][132];
    __shared__ float Ws[16][128];

    int blk = blockIdx.x;
    int win = blk & 255, sb = blk >> 8;
    int s = sb >> 3, b = sb & 7;
    int wy = win >> 4, wx = win & 15;
    int tid = threadIdx.x;

    {
        int t = tid >> 2, q = tid & 3;
        int py = t >> 3, px = t & 7;
        int hh = wy * 8 + py, ww = wx * 8 + px;
        if (s) { hh = (hh + 4) & 127; ww = (ww + 4) & 127; }
        const float* xrow = x + ((size_t)(b * 16384 + hh * 128 + ww)) * 256;
        const float4* xr4 = (const float4*)xrow + q * 16;
        float sum = 0.f, sq = 0.f;
        #pragma unroll
        for (int i = 0; i < 16; i++) {
            float4 v = xr4[i];
            sum += v.x + v.y + v.z + v.w;
            sq  += v.x * v.x + v.y * v.y + v.z * v.z + v.w * v.w;
        }
        sum += __shfl_xor_sync(0xffffffffu, sum, 1);
        sum += __shfl_xor_sync(0xffffffffu, sum, 2);
        sq  += __shfl_xor_sync(0xffffffffu, sq, 1);
        sq  += __shfl_xor_sync(0xffffffffu, sq, 2);
        float mean = sum * (1.f / 256.f);
        float rstd = rsqrtf(sq * (1.f / 256.f) - mean * mean + 1e-5f);

        const float4* xb = (const float4*)(xrow + s * 128 + q * 32);
        const float4* gg = (const float4*)(n1g + s * 128 + q * 32);
        const float4* bb = (const float4*)(n1b + s * 128 + q * 32);
        #pragma unroll
        for (int i = 0; i < 8; i++) {
            float4 v = xb[i], gv = gg[i], bv = bb[i];
            int c = q * 32 + i * 4;
            As[t][c + 0] = (v.x - mean) * rstd * gv.x + bv.x;
            As[t][c + 1] = (v.y - mean) * rstd * gv.y + bv.y;
            As[t][c + 2] = (v.z - mean) * rstd * gv.z + bv.z;
            As[t][c + 3] = (v.w - mean) * rstd * gv.w + bv.w;
        }
    }
    __syncthreads();

    int ty = tid >> 4, tx = tid & 15;
    int t0 = ty * 4, r0 = tx * 8;
    int lr = tid >> 1, lk = (tid & 1) * 8;

    for (int chunk = 0; chunk < 3; chunk++) {
        float acc[4][8];
        #pragma unroll
        for (int i = 0; i < 4; i++)
            #pragma unroll
            for (int j = 0; j < 8; j++) acc[i][j] = 0.f;

        for (int k0 = 0; k0 < 128; k0 += 16) {
            const float4* wsrc = (const float4*)(qkv_w + (size_t)(chunk * 128 + lr) * 128 + k0 + lk);
            float4 w0 = wsrc[0], w1 = wsrc[1];
            __syncthreads();
            Ws[lk + 0][lr] = w0.x; Ws[lk + 1][lr] = w0.y; Ws[lk + 2][lr] = w0.z; Ws[lk + 3][lr] = w0.w;
            Ws[lk + 4][lr] = w1.x; Ws[lk + 5][lr] = w1.y; Ws[lk + 6][lr] = w1.z; Ws[lk + 7][lr] = w1.w;
            __syncthreads();
            #pragma unroll
            for (int kk = 0; kk < 16; kk++) {
                float a0 = As[t0 + 0][k0 + kk];
                float a1 = As[t0 + 1][k0 + kk];
                float a2 = As[t0 + 2][k0 + kk];
                float a3 = As[t0 + 3][k0 + kk];
                float4 b0 = *(const float4*)&Ws[kk][r0];
                float4 b1 = *(const float4*)&Ws[kk][r0 + 4];
                acc[0][0] += a0 * b0.x; acc[0][1] += a0 * b0.y; acc[0][2] += a0 * b0.z; acc[0][3] += a0 * b0.w;
                acc[0][4] += a0 * b1.x; acc[0][5] += a0 * b1.y; acc[0][6] += a0 * b1.z; acc[0][7] += a0 * b1.w;
                acc[1][0] += a1 * b0.x; acc[1][1] += a1 * b0.y; acc[1][2] += a1 * b0.z; acc[1][3] += a1 * b0.w;
                acc[1][4] += a1 * b1.x; acc[1][5] += a1 * b1.y; acc[1][6] += a1 * b1.z; acc[1][7] += a1 * b1.w;
                acc[2][0] += a2 * b0.x; acc[2][1] += a2 * b0.y; acc[2][2] += a2 * b0.z; acc[2][3] += a2 * b0.w;
                acc[2][4] += a2 * b1.x; acc[2][5] += a2 * b1.y; acc[2][6] += a2 * b1.z; acc[2][7] += a2 * b1.w;
                acc[3][0] += a3 * b0.x; acc[3][1] += a3 * b0.y; acc[3][2] += a3 * b0.z; acc[3][3] += a3 * b0.w;
                acc[3][4] += a3 * b1.x; acc[3][5] += a3 * b1.y; acc[3][6] += a3 * b1.z; acc[3][7] += a3 * b1.w;
            }
        }
        float* dst = (chunk == 0) ? PTR_Q : (chunk == 1) ? PTR_K : PTR_V;
        #pragma unroll
        for (int j = 0; j < 8; j++) {
            int r = r0 + j;
            float bias = qkv_b[chunk * 128 + r];
            float4 o = make_float4(acc[0][j] + bias, acc[1][j] + bias, acc[2][j] + bias, acc[3][j] + bias);
            *(float4*)&dst[((size_t)(sb * 128 + r) * 256 + win) * 64 + t0] = o;
        }
    }
}

// ---------------------------------------------------------------------------
// Kernel 2: finite-difference gradient scores (524288 items, grid (2048,2)).
// ---------------------------------------------------------------------------
__global__ __launch_bounds__(256) void k_grad()
{
    int idx = blockIdx.x * 256 + threadIdx.x;
    const float* src = blockIdx.y ? PTR_K : PTR_Q;
    float*       dst = blockIdx.y ? g_kg : g_qg;
    float scale = blockIdx.y ? 1.f : 0.17677669529663687f;

    float v[64];
    const float4* p = (const float4*)(src + (size_t)idx * 64);
    #pragma unroll
    for (int i = 0; i < 16; i++) {
        float4 t = p[i];
        v[i * 4 + 0] = t.x; v[i * 4 + 1] = t.y; v[i * 4 + 2] = t.z; v[i * 4 + 3] = t.w;
    }
    float sc = 0.f;
    #pragma unroll
    for (int py = 0; py < 8; py++)
        #pragma unroll
        for (int px = 0; px < 8; px++) {
            float t = v[py * 8 + px];
            float gx = px ? (t - v[py * 8 + px - 1]) : t;
            float gy = py ? (t - v[(py - 1) * 8 + px]) : t;
            sc += fabsf(gx) + fabsf(gy);
        }
    dst[idx] = sc * scale;
}

// ---------------------------------------------------------------------------
// Kernel 3: inter-window rank-1 softmax attention (fp32).
// ---------------------------------------------------------------------------
__global__ __launch_bounds__(256) void k_attn()
{
    __shared__ float kg_s[256];
    __shared__ float Vs[64 * 64];
    __shared__ float smin[8], smax[8];

    int rest = blockIdx.x;
    int i = threadIdx.x;

    kg_s[i] = g_kg[(size_t)rest * 256 + i];
    float kmin = kg_s[i], kmax = kmin;
    #pragma unroll
    for (int o = 16; o; o >>= 1) {
        kmin = fminf(kmin, __shfl_xor_sync(0xffffffffu, kmin, o));
        kmax = fmaxf(kmax, __shfl_xor_sync(0xffffffffu, kmax, o));
    }
    if ((i & 31) == 0) { smin[i >> 5] = kmin; smax[i >> 5] = kmax; }
    __syncthreads();
    kmin = smin[0]; kmax = smax[0];
    #pragma unroll
    for (int w = 1; w < 8; w++) { kmin = fminf(kmin, smin[w]); kmax = fmaxf(kmax, smax[w]); }

    float qgi = g_qg[(size_t)rest * 256 + i];
    float m = (qgi >= 0.f) ? qgi * kmax : qgi * kmin;

    float acc[64];
    #pragma unroll
    for (int t = 0; t < 64; t++) acc[t] = 0.f;
    float Z = 0.f;

    const float* Vbase = PTR_V;
    for (int jc = 0; jc < 4; jc++) {
        __syncthreads();
        const float4* vsrc = (const float4*)(Vbase + ((size_t)rest * 256 + jc * 64) * 64);
        float4* vdst = (float4*)Vs;
        #pragma unroll
        for (int u = 0; u < 4; u++) vdst[i + u * 256] = vsrc[i + u * 256];
        __syncthreads();
        #pragma unroll 2
        for (int j = 0; j < 64; j++) {
            float e = __expf(qgi * kg_s[jc * 64 + j] - m);
            Z += e;
            const float4* vr = (const float4*)(Vs + j * 64);
            #pragma unroll
            for (int t = 0; t < 16; t++) {
                float4 vv = vr[t];
                acc[t * 4 + 0] += e * vv.x;
                acc[t * 4 + 1] += e * vv.y;
                acc[t * 4 + 2] += e * vv.z;
                acc[t * 4 + 3] += e * vv.w;
            }
        }
    }
    float inv = 1.f / Z;
    float4* od = (float4*)(PTR_ATTN + ((size_t)rest * 256 + i) * 64);
    #pragma unroll
    for (int t = 0; t < 16; t++)
        od[t] = make_float4(acc[t * 4] * inv, acc[t * 4 + 1] * inv,
                            acc[t * 4 + 2] * inv, acc[t * 4 + 3] * inv);
}

// ---------------------------------------------------------------------------
// Kernel 4: proj GEMM + window reverse + residual -> y (S0).
// ---------------------------------------------------------------------------
__global__ __launch_bounds__(256) void k_proj(
    const float* __restrict__ x, const float* __restrict__ proj_w, const float* __restrict__ proj_b)
{
    __shared__ float As[64][132];
    __shared__ float Ws[16][128];

    int blk = blockIdx.x;
    int win = blk & 255, sb = blk >> 8;
    int s = sb >> 3, b = sb & 7;
    int wy = win >> 4, wx = win & 15;
    int tid = threadIdx.x;

    {
        int c = tid >> 1, half = tid & 1;
        const float4* src = (const float4*)(PTR_ATTN + ((size_t)(sb * 128 + c) * 256 + win) * 64 + half * 32);
        #pragma unroll
        for (int u = 0; u < 8; u++) {
            float4 v = src[u];
            int p = half * 32 + u * 4;
            As[p + 0][c] = v.x; As[p + 1][c] = v.y; As[p + 2][c] = v.z; As[p + 3][c] = v.w;
        }
    }
    __syncthreads();

    int ty = tid >> 4, tx = tid & 15;
    int t0 = ty * 4, r0 = tx * 8;
    int lr = tid >> 1, lk = (tid & 1) * 8;

    float acc[4][8];
    #pragma unroll
    for (int i = 0; i < 4; i++)
        #pragma unroll
        for (int j = 0; j < 8; j++) acc[i][j] = 0.f;

    for (int k0 = 0; k0 < 128; k0 += 16) {
        const float4* wsrc = (const float4*)(proj_w + (size_t)lr * 128 + k0 + lk);
        float4 w0 = wsrc[0], w1 = wsrc[1];
        __syncthreads();
        Ws[lk + 0][lr] = w0.x; Ws[lk + 1][lr] = w0.y; Ws[lk + 2][lr] = w0.z; Ws[lk + 3][lr] = w0.w;
        Ws[lk + 4][lr] = w1.x; Ws[lk + 5][lr] = w1.y; Ws[lk + 6][lr] = w1.z; Ws[lk + 7][lr] = w1.w;
        __syncthreads();
        #pragma unroll
        for (int kk = 0; kk < 16; kk++) {
            float a0 = As[t0 + 0][k0 + kk];
            float a1 = As[t0 + 1][k0 + kk];
            float a2 = As[t0 + 2][k0 + kk];
            float a3 = As[t0 + 3][k0 + kk];
            float4 b0 = *(const float4*)&Ws[kk][r0];
            float4 b1 = *(const float4*)&Ws[kk][r0 + 4];
            acc[0][0] += a0 * b0.x; acc[0][1] += a0 * b0.y; acc[0][2] += a0 * b0.z; acc[0][3] += a0 * b0.w;
            acc[0][4] += a0 * b1.x; acc[0][5] += a0 * b1.y; acc[0][6] += a0 * b1.z; acc[0][7] += a0 * b1.w;
            acc[1][0] += a1 * b0.x; acc[1][1] += a1 * b0.y; acc[1][2] += a1 * b0.z; acc[1][3] += a1 * b0.w;
            acc[1][4] += a1 * b1.x; acc[1][5] += a1 * b1.y; acc[1][6] += a1 * b1.z; acc[1][7] += a1 * b1.w;
            acc[2][0] += a2 * b0.x; acc[2][1] += a2 * b0.y; acc[2][2] += a2 * b0.z; acc[2][3] += a2 * b0.w;
            acc[2][4] += a2 * b1.x; acc[2][5] += a2 * b1.y; acc[2][6] += a2 * b1.z; acc[2][7] += a2 * b1.w;
            acc[3][0] += a3 * b0.x; acc[3][1] += a3 * b0.y; acc[3][2] += a3 * b0.z; acc[3][3] += a3 * b0.w;
            acc[3][4] += a3 * b1.x; acc[3][5] += a3 * b1.y; acc[3][6] += a3 * b1.z; acc[3][7] += a3 * b1.w;
        }
    }

    float b0b = proj_b[r0 + 0], b1b = proj_b[r0 + 1], b2b = proj_b[r0 + 2], b3b = proj_b[r0 + 3];
    float b4b = proj_b[r0 + 4], b5b = proj_b[r0 + 5], b6b = proj_b[r0 + 6], b7b = proj_b[r0 + 7];
    #pragma unroll
    for (int ii = 0; ii < 4; ii++) {
        int t = t0 + ii;
        int py = t >> 3, px = t & 7;
        int hh = wy * 8 + py, ww = wx * 8 + px;
        if (s) { hh = (hh + 4) & 127; ww = (ww + 4) & 127; }
        size_t base = ((size_t)(b * 16384 + hh * 128 + ww)) * 256 + s * 128 + r0;
        float4 x0 = *(const float4*)(x + base);
        float4 x1 = *(const float4*)(x + base + 4);
        float4 o0 = make_float4(acc[ii][0] + b0b + x0.x, acc[ii][1] + b1b + x0.y,
                                acc[ii][2] + b2b + x0.z, acc[ii][3] + b3b + x0.w);
        float4 o1 = make_float4(acc[ii][4] + b4b + x1.x, acc[ii][5] + b5b + x1.y,
                                acc[ii][6] + b6b + x1.z, acc[ii][7] + b7b + x1.w);
        *(float4*)(PTR_Y + base) = o0;
        *(float4*)(PTR_Y + base + 4) = o1;
    }
}

// ---------------------------------------------------------------------------
// Kernel 5: LN2 -> bf16 Yn (token-major) in S3.
// ---------------------------------------------------------------------------
__global__ __launch_bounds__(256) void k_ln2(
    const float* __restrict__ n2g, const float* __restrict__ n2b)
{
    int token = blockIdx.x * 64 + (threadIdx.x >> 2);
    int q = threadIdx.x & 3;
    const float* yrow = PTR_Y + (size_t)token * 256;
    const float4* yr4 = (const float4*)yrow + q * 16;
    float sum = 0.f, sq = 0.f;
    #pragma unroll
    for (int i = 0; i < 16; i++) {
        float4 v = yr4[i];
        sum += v.x + v.y + v.z + v.w;
        sq  += v.x * v.x + v.y * v.y + v.z * v.z + v.w * v.w;
    }
    sum += __shfl_xor_sync(0xffffffffu, sum, 1);
    sum += __shfl_xor_sync(0xffffffffu, sum, 2);
    sq  += __shfl_xor_sync(0xffffffffu, sq, 1);
    sq  += __shfl_xor_sync(0xffffffffu, sq, 2);
    float mean = sum * (1.f / 256.f);
    float rstd = rsqrtf(sq * (1.f / 256.f) - mean * mean + 1e-5f);

    const float4* ys = (const float4*)(yrow + q * 64);
    const float4* gs = (const float4*)(n2g + q * 64);
    const float4* bs = (const float4*)(n2b + q * 64);
    uint32_t* dst = (uint32_t*)(PTR_YN + (size_t)token * 256 + q * 64);
    #pragma unroll
    for (int i = 0; i < 16; i++) {
        float4 v = ys[i], g = gs[i], b = bs[i];
        float o0 = (v.x - mean) * rstd * g.x + b.x;
        float o1 = (v.y - mean) * rstd * g.y + b.y;
        float o2 = (v.z - mean) * rstd * g.z + b.z;
        float o3 = (v.w - mean) * rstd * g.w + b.w;
        uint32_t u0 = (uint32_t)__bfloat16_as_ushort(__float2bfloat16(o0))
                    | ((uint32_t)__bfloat16_as_ushort(__float2bfloat16(o1)) << 16);
        uint32_t u1 = (uint32_t)__bfloat16_as_ushort(__float2bfloat16(o2))
                    | ((uint32_t)__bfloat16_as_ushort(__float2bfloat16(o3)) << 16);
        dst[i * 2 + 0] = u0;
        dst[i * 2 + 1] = u1;
    }
}

// ---------------------------------------------------------------------------
// Kernel 5b: convert fc1/fc2 weights to bf16.
// ---------------------------------------------------------------------------
__global__ __launch_bounds__(256) void k_cvt(
    const float* __restrict__ w1, const float* __restrict__ w2)
{
    int i = blockIdx.x * 256 + threadIdx.x;
    if (i < 131072) g_w1b[i] = __float2bfloat16(w1[i]);
    else            g_w2b[i - 131072] = __float2bfloat16(w2[i - 131072]);
}

// ---------------------------------------------------------------------------
// Kernel 6: fc1 via mma.sync bf16. Tile M=128, N=128, K=256.
// Grid (1024 M-tiles, 4 N-tiles). Epilogue: +bias, fp32 NCHW into S1+S2.
// Dynamic smem: A[128][264] + B[128][264] bf16 = 135168 B.
// ---------------------------------------------------------------------------
__global__ __launch_bounds__(256, 1) void k_fc1_mma(const float* __restrict__ fc1_b_)
{
    extern __shared__ char smc[];
    __nv_bfloat16* Asm = (__nv_bfloat16*)smc;
    __nv_bfloat16* Bsm = Asm + 128 * TSTRIDE;
    uint32_t sA = smem_u32(Asm), sB = smem_u32(Bsm);

    int tid = threadIdx.x, wid = tid >> 5, lane = tid & 31;
    int wm = wid >> 1, wn = wid & 1;
    int mt = blockIdx.x, nt = blockIdx.y;

    const __nv_bfloat16* Asrc = PTR_YN + (size_t)mt * 128 * 256;
    const __nv_bfloat16* Bsrc = g_w1b + (size_t)nt * 128 * 256;
    for (int idx = tid; idx < 4096; idx += 256) {
        int row = idx >> 5, c8 = (idx & 31) << 3;
        *(uint4*)(Asm + row * TSTRIDE + c8) = *(const uint4*)(Asrc + row * 256 + c8);
        *(uint4*)(Bsm + row * TSTRIDE + c8) = *(const uint4*)(Bsrc + row * 256 + c8);
    }
    __syncthreads();

    float c[2][8][4];
    #pragma unroll
    for (int i = 0; i < 2; i++)
        #pragma unroll
        for (int j = 0; j < 8; j++)
            #pragma unroll
            for (int k = 0; k < 4; k++) c[i][j][k] = 0.f;

    mma_tile_128(sA, sB, lane, wm, wn, c);
    __syncthreads();

    // stage T[n][token] fp32 (reuses A+B smem region)
    float* T = (float*)smc;   // [128][132]
    #pragma unroll
    for (int mi = 0; mi < 2; mi++)
        #pragma unroll
        for (int n8 = 0; n8 < 8; n8++) {
            int rt = wm * 32 + mi * 16 + (lane >> 2);
            int cn = wn * 64 + n8 * 8 + (lane & 3) * 2;
            T[cn * 132 + rt]           = c[mi][n8][0];
            T[(cn + 1) * 132 + rt]     = c[mi][n8][1];
            T[cn * 132 + rt + 8]       = c[mi][n8][2];
            T[(cn + 1) * 132 + rt + 8] = c[mi][n8][3];
        }
    __syncthreads();

    int token0 = mt * 128;
    int b = token0 >> 14;
    int hw0 = token0 & 16383;
    int n = tid >> 1, half = tid & 1;
    float bias = fc1_b_[nt * 128 + n];
    float* dst = PTR_FC1 + ((size_t)(b * 512 + nt * 128 + n)) * 16384 + hw0 + half * 64;
    const float* trow = T + n * 132 + half * 64;
    #pragma unroll
    for (int u = 0; u < 16; u++) {
        float4 o = make_float4(trow[u * 4 + 0] + bias, trow[u * 4 + 1] + bias,
                               trow[u * 4 + 2] + bias, trow[u * 4 + 3] + bias);
        *(float4*)(dst + u * 4) = o;
    }
}

// ---------------------------------------------------------------------------
// Kernel 7: depthwise 3x3 conv + gate (fp32 NCHW, unchanged).
// ---------------------------------------------------------------------------
__global__ __launch_bounds__(256) void k_dwgate(
    const float* __restrict__ dw_w, const float* __restrict__ dw_b)
{
    __shared__ float in0[6][130];
    __shared__ float in1[6][130];
    __shared__ float wsm[2][9];
    __shared__ float bsm[2];

    int y0 = blockIdx.x * 4;
    int c  = blockIdx.y;
    int b  = blockIdx.z;
    int tid = threadIdx.x;

    if (tid < 18) { int ch = tid / 9, k = tid - ch * 9; wsm[ch][k] = dw_w[(size_t)(c + ch * 256) * 9 + k]; }
    if (tid < 2) bsm[tid] = dw_b[c + tid * 256];

    for (int e = tid; e < 2 * 6 * 130; e += 256) {
        int ch = e / 780;
        int rem = e - ch * 780;
        int rr = rem / 130;
        int cc = rem - rr * 130;
        int gy = y0 - 1 + rr, gx = cc - 1;
        float v = 0.f;
        if (gy >= 0 && gy < 128 && gx >= 0 && gx < 128)
            v = PTR_FC1[(size_t)(b * 512 + c + ch * 256) * 16384 + gy * 128 + gx];
        if (ch) in1[rr][cc] = v; else in0[rr][cc] = v;
    }
    __syncthreads();

    #pragma unroll
    for (int k = 0; k < 2; k++) {
        int o = tid + k * 256;
        int yy = o >> 7, xx = o & 127;
        float c0 = bsm[0], c1 = bsm[1];
        #pragma unroll
        for (int ky = 0; ky < 3; ky++)
            #pragma unroll
            for (int kx = 0; kx < 3; kx++) {
                c0 += wsm[0][ky * 3 + kx] * in0[yy + ky][xx + kx];
                c1 += wsm[1][ky * 3 + kx] * in1[yy + ky][xx + kx];
            }
        PTR_GATE[(size_t)(b * 256 + c) * 16384 + (y0 + yy) * 128 + xx] = c0 * c1;
    }
}

// ---------------------------------------------------------------------------
// Kernel 8: gate NCHW fp32 -> token-major bf16 (gate_t in S1).
// ---------------------------------------------------------------------------
__global__ __launch_bounds__(256) void k_tr()
{
    __shared__ float t[32][33];
    int hw0 = blockIdx.x * 32, c0 = blockIdx.y * 32, b = blockIdx.z;
    int tx = threadIdx.x & 31, ty = threadIdx.x >> 5;
    #pragma unroll
    for (int i = 0; i < 4; i++) {
        int c = c0 + ty + i * 8;
        t[ty + i * 8][tx] = PTR_GATE[((size_t)(b * 256 + c)) * 16384 + hw0 + tx];
    }
    __syncthreads();
    #pragma unroll
    for (int i = 0; i < 4; i++) {
        int row = ty + i * 8;
        PTR_GT[((size_t)(b * 16384 + hw0 + row)) * 256 + c0 + tx] = __float2bfloat16(t[tx][row]);
    }
}

// ---------------------------------------------------------------------------
// Kernel 9: fc2 via mma.sync bf16. Tile M=128, N=128, K=256. Grid (1024, 2).
// Epilogue: +bias +residual(Y) -> d_out (token-major).
// ---------------------------------------------------------------------------
__global__ __launch_bounds__(256, 1) void k_fc2_mma(
    const float* __restrict__ fc2_b_, float* __restrict__ out)
{
    extern __shared__ char smc[];
    __nv_bfloat16* Asm = (__nv_bfloat16*)smc;
    __nv_bfloat16* Bsm = Asm + 128 * TSTRIDE;
    uint32_t sA = smem_u32(Asm), sB = smem_u32(Bsm);

    int tid = threadIdx.x, wid = tid >> 5, lane = tid & 31;
    int wm = wid >> 1, wn = wid & 1;
    int mt = blockIdx.x, nt = blockIdx.y;

    const __nv_bfloat16* Asrc = PTR_GT + (size_t)mt * 128 * 256;
    const __nv_bfloat16* Bsrc = g_w2b + (size_t)nt * 128 * 256;
    for (int idx = tid; idx < 4096; idx += 256) {
        int row = idx >> 5, c8 = (idx & 31) << 3;
        *(uint4*)(Asm + row * TSTRIDE + c8) = *(const uint4*)(Asrc + row * 256 + c8);
        *(uint4*)(Bsm + row * TSTRIDE + c8) = *(const uint4*)(Bsrc + row * 256 + c8);
    }
    __syncthreads();

    float c[2][8][4];
    #pragma unroll
    for (int i = 0; i < 2; i++)
        #pragma unroll
        for (int j = 0; j < 8; j++)
            #pragma unroll
            for (int k = 0; k < 4; k++) c[i][j][k] = 0.f;

    mma_tile_128(sA, sB, lane, wm, wn, c);
    __syncthreads();

    // stage T[token][n]
    float* T = (float*)smc;   // [128][132]
    #pragma unroll
    for (int mi = 0; mi < 2; mi++)
        #pragma unroll
        for (int n8 = 0; n8 < 8; n8++) {
            int rt = wm * 32 + mi * 16 + (lane >> 2);
            int cn = wn * 64 + n8 * 8 + (lane & 3) * 2;
            T[rt * 132 + cn]           = c[mi][n8][0];
            T[rt * 132 + cn + 1]       = c[mi][n8][1];
            T[(rt + 8) * 132 + cn]     = c[mi][n8][2];
            T[(rt + 8) * 132 + cn + 1] = c[mi][n8][3];
        }
    __syncthreads();

    size_t token0 = (size_t)mt * 128;
    int m = tid >> 1, half = tid & 1;
    int n0 = nt * 128 + half * 64;
    size_t base = (token0 + m) * 256 + n0;
    const float* trow = T + m * 132 + half * 64;
    #pragma unroll
    for (int u = 0; u < 16; u++) {
        float4 y = *(const float4*)(PTR_Y + base + u * 4);
        float4 o;
        o.x = trow[u * 4 + 0] + fc2_b_[n0 + u * 4 + 0] + y.x;
        o.y = trow[u * 4 + 1] + fc2_b_[n0 + u * 4 + 1] + y.y;
        o.z = trow[u * 4 + 2] + fc2_b_[n0 + u * 4 + 2] + y.z;
        o.w = trow[u * 4 + 3] + fc2_b_[n0 + u * 4 + 3] + y.w;
        *(float4*)(out + base + u * 4) = o;
    }
}

// ---------------------------------------------------------------------------
extern "C" void kernel_launch(void* const* d_in, const int* in_sizes, int n_in,
                              void* d_out, int out_size)
{
    const float* x      = (const float*)d_in[0];
    const float* n1g    = (const float*)d_in[1];
    const float* n1b    = (const float*)d_in[2];
    const float* qkv_w  = (const float*)d_in[3];
    const float* qkv_b  = (const float*)d_in[4];
    const float* proj_w = (const float*)d_in[5];
    const float* proj_b = (const float*)d_in[6];
    const float* n2g    = (const float*)d_in[7];
    const float* n2b    = (const float*)d_in[8];
    const float* fc1_w  = (const float*)d_in[9];
    const float* fc1_b  = (const float*)d_in[10];
    const float* dw_w   = (const float*)d_in[11];
    const float* dw_b   = (const float*)d_in[12];
    const float* fc2_w  = (const float*)d_in[13];
    const float* fc2_b  = (const float*)d_in[14];
    float* out = (float*)d_out;

    cudaFuncSetAttribute(k_fc1_mma, cudaFuncAttributeMaxDynamicSharedMemorySize, 135168);
    cudaFuncSetAttribute(k_fc2_mma, cudaFuncAttributeMaxDynamicSharedMemorySize, 135168);

    k_cvt<<<768, 256>>>(fc1_w, fc2_w);
    k_qkv<<<4096, 256>>>(x, n1g, n1b, qkv_w, qkv_b);
    k_grad<<<dim3(2048, 2), 256>>>();
    k_attn<<<2048, 256>>>();
    k_proj<<<4096, 256>>>(x, proj_w, proj_b);
    k_ln2<<<2048, 256>>>(n2g, n2b);
    k_fc1_mma<<<dim3(1024, 4), 256, 135168>>>(fc1_b);
    k_dwgate<<<dim3(32, 256, 8), 256>>>(dw_w, dw_b);
    k_tr<<<dim3(512, 8, 8), 256>>>();
    k_fc2_mma<<<dim3(1024, 2), 256, 135168>>>(fc2_b, out);
}

// round 9
// speedup vs baseline: 1.4390x; 1.0383x over previous
#include <cuda_runtime.h>
#include <cuda_bf16.h>
#include <cstdint>

// ---------------------------------------------------------------------------
// B=8, H=W=128, L=16384, DIM=256, C_ATTN=128, WS=8, SHIFT=4,
// HEADS=4, HD=32, HIDDEN=512, 256 windows x 64 tokens, 2 shift branches.
//
// Scratch slots (128MB each):
//   S0: Q  -> y (residual, live to end)
//   S1: K  -> fc1 out (lower)  -> gate_t bf16 (after dwgate)
//   S2: V  -> fc1 out (upper)
//   S3: attn-out -> Yn bf16 (ln2 out) -> gate fp32 NCHW (dwgate out)
// ---------------------------------------------------------------------------

#define SLOT 33554432
__device__ float g_scratch[4 * SLOT];
__device__ float g_qg[524288];
__device__ float g_kg[524288];
__device__ __nv_bfloat16 g_w1b[512 * 256];
__device__ __nv_bfloat16 g_w2b[256 * 256];
__device__ __nv_bfloat16 g_wpb[128 * 128];

#define PTR_Q    (g_scratch)
#define PTR_K    (g_scratch + SLOT)
#define PTR_V    (g_scratch + 2 * SLOT)
#define PTR_ATTN (g_scratch + 3 * SLOT)
#define PTR_Y    (g_scratch)
#define PTR_FC1  (g_scratch + SLOT)
#define PTR_GATE (g_scratch + 3 * SLOT)
#define PTR_YN   ((__nv_bfloat16*)(g_scratch + 3 * SLOT))
#define PTR_GT   ((__nv_bfloat16*)(g_scratch + SLOT))

// ------------------------------ helpers ------------------------------------
__device__ __forceinline__ uint32_t smem_u32(const void* p) {
    uint32_t a;
    asm("{ .reg .u64 t; cvta.to.shared.u64 t, %1; cvt.u32.u64 %0, t; }" : "=r"(a) : "l"(p));
    return a;
}
__device__ __forceinline__ void ldmx4(uint32_t* r, uint32_t addr) {
    asm volatile("ldmatrix.sync.aligned.m8n8.x4.shared.b16 {%0,%1,%2,%3}, [%4];"
        : "=r"(r[0]), "=r"(r[1]), "=r"(r[2]), "=r"(r[3]) : "r"(addr));
}
__device__ __forceinline__ void mma16816(float* c, const uint32_t* a, uint32_t b0, uint32_t b1) {
    asm volatile("mma.sync.aligned.m16n8k16.row.col.f32.bf16.bf16.f32 "
        "{%0,%1,%2,%3}, {%4,%5,%6,%7}, {%8,%9}, {%0,%1,%2,%3};"
        : "+f"(c[0]), "+f"(c[1]), "+f"(c[2]), "+f"(c[3])
        : "r"(a[0]), "r"(a[1]), "r"(a[2]), "r"(a[3]), "r"(b0), "r"(b1));
}
__device__ __forceinline__ uint32_t f2tf32(float f) {
    uint32_t r;
    asm("cvt.rna.tf32.f32 %0, %1;" : "=r"(r) : "f"(f));
    return r;
}
__device__ __forceinline__ void mma_tf32(float* c, const uint32_t* a, uint32_t b0, uint32_t b1) {
    asm volatile("mma.sync.aligned.m16n8k8.row.col.f32.tf32.tf32.f32 "
        "{%0,%1,%2,%3}, {%4,%5,%6,%7}, {%8,%9}, {%0,%1,%2,%3};"
        : "+f"(c[0]), "+f"(c[1]), "+f"(c[2]), "+f"(c[3])
        : "r"(a[0]), "r"(a[1]), "r"(a[2]), "r"(a[3]), "r"(b0), "r"(b1));
}

// 128x128 bf16 mma core. smem tiles row-major with 264-elem stride (528B = 33*16B).
// Warp grid 4x2: warp (wm, wn) owns rows [wm*32,+32) x cols [wn*64,+64).
#define TSTRIDE 264
#define TSTRB   (TSTRIDE * 2)

template<int KMAX>
__device__ __forceinline__ void mma_tile_bf16(
    uint32_t sA, uint32_t sB, int lane, int wm, int wn, float (&c)[2][8][4])
{
    uint32_t aRowB = sA + (uint32_t)(wm * 32 + (lane & 15)) * TSTRB + (uint32_t)((lane >> 4) << 4);
    uint32_t bRowB = sB + (uint32_t)(wn * 64 + (lane & 7) + ((lane >> 4) << 3)) * TSTRB
                   + (uint32_t)(((lane >> 3) & 1) << 4);
    #pragma unroll
    for (int k0 = 0; k0 < KMAX; k0 += 16) {
        uint32_t a[2][4];
        #pragma unroll
        for (int mi = 0; mi < 2; mi++)
            ldmx4(a[mi], aRowB + (uint32_t)(mi * 16) * TSTRB + k0 * 2);
        uint32_t bf[4][4];
        #pragma unroll
        for (int nf = 0; nf < 4; nf++)
            ldmx4(bf[nf], bRowB + (uint32_t)(nf * 16) * TSTRB + k0 * 2);
        #pragma unroll
        for (int mi = 0; mi < 2; mi++)
            #pragma unroll
            for (int n8 = 0; n8 < 8; n8++)
                mma16816(c[mi][n8], a[mi], bf[n8 >> 1][(n8 & 1) * 2], bf[n8 >> 1][(n8 & 1) * 2 + 1]);
    }
}

// ---------------------------------------------------------------------------
// Kernel 1: LN1 + window partition (+roll) + QKV GEMM via 3-pass TF32 mma.
// Block = (sb, window-pair): M=128 tokens, N=128 x 3 chunks (q,k,v), K=128.
// ---------------------------------------------------------------------------
__global__ __launch_bounds__(256, 1) void k_qkv_mma(
    const float* __restrict__ x, const float* __restrict__ n1g, const float* __restrict__ n1b,
    const float* __restrict__ qkv_w, const float* __restrict__ qkv_b)
{
    extern __shared__ float smf[];
    float* Asm = smf;               // [128][132] LN1 branch output (persists all chunks)
    float* Bsm = smf + 128 * 132;   // [128][132] weight chunk / T staging

    int tid = threadIdx.x, wid = tid >> 5, lane = tid & 31;
    int wm = wid >> 1, wn = wid & 1;
    int blk = blockIdx.x;
    int wp = blk & 127, sb = blk >> 7;
    int s = sb >> 3, b = sb & 7;

    // ---- LN1 for 128 tokens (2 windows), branch s channels into Asm ----
    {
        int r = tid >> 1, q = tid & 1;
        int w2 = r >> 6, p = r & 63;
        int win = wp * 2 + w2;
        int wy = win >> 4, wx = win & 15;
        int py = p >> 3, px = p & 7;
        int hh = wy * 8 + py, ww = wx * 8 + px;
        if (s) { hh = (hh + 4) & 127; ww = (ww + 4) & 127; }
        const float* xrow = x + ((size_t)(b * 16384 + hh * 128 + ww)) * 256;
        const float4* xr4 = (const float4*)xrow + q * 32;
        float sum = 0.f, sq = 0.f;
        #pragma unroll
        for (int i = 0; i < 32; i++) {
            float4 v = xr4[i];
            sum += v.x + v.y + v.z + v.w;
            sq  += v.x * v.x + v.y * v.y + v.z * v.z + v.w * v.w;
        }
        sum += __shfl_xor_sync(0xffffffffu, sum, 1);
        sq  += __shfl_xor_sync(0xffffffffu, sq, 1);
        float mean = sum * (1.f / 256.f);
        float rstd = rsqrtf(sq * (1.f / 256.f) - mean * mean + 1e-5f);

        const float4* xb = (const float4*)(xrow + s * 128 + q * 64);
        const float4* gg = (const float4*)(n1g + s * 128 + q * 64);
        const float4* bb = (const float4*)(n1b + s * 128 + q * 64);
        float* arow = Asm + r * 132 + q * 64;
        #pragma unroll
        for (int i = 0; i < 16; i++) {
            float4 v = xb[i], g = gg[i], bv = bb[i];
            arow[i * 4 + 0] = (v.x - mean) * rstd * g.x + bv.x;
            arow[i * 4 + 1] = (v.y - mean) * rstd * g.y + bv.y;
            arow[i * 4 + 2] = (v.z - mean) * rstd * g.z + bv.z;
            arow[i * 4 + 3] = (v.w - mean) * rstd * g.w + bv.w;
        }
    }

    for (int chunk = 0; chunk < 3; chunk++) {
        __syncthreads();   // Asm ready (chunk 0) / T reads done (chunk>0)
        {
            int n = tid >> 1, half = tid & 1;
            const float4* src = (const float4*)(qkv_w + (size_t)(chunk * 128 + n) * 128 + half * 64);
            float* drow = Bsm + n * 132 + half * 64;
            #pragma unroll
            for (int i = 0; i < 16; i++) {
                float4 v = src[i];
                drow[i * 4 + 0] = v.x; drow[i * 4 + 1] = v.y;
                drow[i * 4 + 2] = v.z; drow[i * 4 + 3] = v.w;
            }
        }
        __syncthreads();

        float c[2][8][4];
        #pragma unroll
        for (int i = 0; i < 2; i++)
            #pragma unroll
            for (int j = 0; j < 8; j++)
                #pragma unroll
                for (int k = 0; k < 4; k++) c[i][j][k] = 0.f;

        for (int k0 = 0; k0 < 128; k0 += 8) {
            uint32_t ahi[2][4], alo[2][4];
            #pragma unroll
            for (int mi = 0; mi < 2; mi++) {
                int r0 = wm * 32 + mi * 16 + (lane >> 2);
                int cc = k0 + (lane & 3);
                float a0 = Asm[r0 * 132 + cc];
                float a1 = Asm[(r0 + 8) * 132 + cc];
                float a2 = Asm[r0 * 132 + cc + 4];
                float a3 = Asm[(r0 + 8) * 132 + cc + 4];
                ahi[mi][0] = f2tf32(a0); alo[mi][0] = f2tf32(a0 - __uint_as_float(ahi[mi][0]));
                ahi[mi][1] = f2tf32(a1); alo[mi][1] = f2tf32(a1 - __uint_as_float(ahi[mi][1]));
                ahi[mi][2] = f2tf32(a2); alo[mi][2] = f2tf32(a2 - __uint_as_float(ahi[mi][2]));
                ahi[mi][3] = f2tf32(a3); alo[mi][3] = f2tf32(a3 - __uint_as_float(ahi[mi][3]));
            }
            #pragma unroll
            for (int ni = 0; ni < 8; ni++) {
                int n = wn * 64 + ni * 8 + (lane >> 2);
                int k = k0 + (lane & 3);
                float b0f = Bsm[n * 132 + k];
                float b1f = Bsm[n * 132 + k + 4];
                uint32_t bh0 = f2tf32(b0f), bh1 = f2tf32(b1f);
                uint32_t bl0 = f2tf32(b0f - __uint_as_float(bh0));
                uint32_t bl1 = f2tf32(b1f - __uint_as_float(bh1));
                #pragma unroll
                for (int mi = 0; mi < 2; mi++) {
                    mma_tf32(c[mi][ni], ahi[mi], bh0, bh1);
                    mma_tf32(c[mi][ni], ahi[mi], bl0, bl1);
                    mma_tf32(c[mi][ni], alo[mi], bh0, bh1);
                }
            }
        }
        __syncthreads();   // all mma reads of Bsm done

        // stage T[n][token] in Bsm region
        float* T = Bsm;
        #pragma unroll
        for (int mi = 0; mi < 2; mi++)
            #pragma unroll
            for (int n8 = 0; n8 < 8; n8++) {
                int rt = wm * 32 + mi * 16 + (lane >> 2);
                int cn = wn * 64 + n8 * 8 + (lane & 3) * 2;
                T[cn * 132 + rt]           = c[mi][n8][0];
                T[(cn + 1) * 132 + rt]     = c[mi][n8][1];
                T[cn * 132 + rt + 8]       = c[mi][n8][2];
                T[(cn + 1) * 132 + rt + 8] = c[mi][n8][3];
            }
        __syncthreads();

        float* dst = (chunk == 0) ? PTR_Q : (chunk == 1) ? PTR_K : PTR_V;
        int rr = tid >> 1, half = tid & 1;
        float bias = qkv_b[chunk * 128 + rr];
        float* drow = dst + ((size_t)(sb * 128 + rr) * 256 + wp * 2) * 64 + half * 64;
        const float* trow = T + rr * 132 + half * 64;
        #pragma unroll
        for (int u = 0; u < 16; u++) {
            float4 o = make_float4(trow[u * 4 + 0] + bias, trow[u * 4 + 1] + bias,
                                   trow[u * 4 + 2] + bias, trow[u * 4 + 3] + bias);
            *(float4*)(drow + u * 4) = o;
        }
    }
}

// ---------------------------------------------------------------------------
// Kernel 2: finite-difference gradient scores (524288 items, grid (2048,2)).
// ---------------------------------------------------------------------------
__global__ __launch_bounds__(256) void k_grad()
{
    int idx = blockIdx.x * 256 + threadIdx.x;
    const float* src = blockIdx.y ? PTR_K : PTR_Q;
    float*       dst = blockIdx.y ? g_kg : g_qg;
    float scale = blockIdx.y ? 1.f : 0.17677669529663687f;

    float v[64];
    const float4* p = (const float4*)(src + (size_t)idx * 64);
    #pragma unroll
    for (int i = 0; i < 16; i++) {
        float4 t = p[i];
        v[i * 4 + 0] = t.x; v[i * 4 + 1] = t.y; v[i * 4 + 2] = t.z; v[i * 4 + 3] = t.w;
    }
    float sc = 0.f;
    #pragma unroll
    for (int py = 0; py < 8; py++)
        #pragma unroll
        for (int px = 0; px < 8; px++) {
            float t = v[py * 8 + px];
            float gx = px ? (t - v[py * 8 + px - 1]) : t;
            float gy = py ? (t - v[(py - 1) * 8 + px]) : t;
            sc += fabsf(gx) + fabsf(gy);
        }
    dst[idx] = sc * scale;
}

// ---------------------------------------------------------------------------
// Kernel 3: inter-window rank-1 softmax attention (fp32).
// 512 threads per rest: thread = (dest window i = tid>>1, t-half th = tid&1).
// acc[32] per thread (halved register pressure vs acc[64]).
// ---------------------------------------------------------------------------
__global__ __launch_bounds__(512) void k_attn()
{
    __shared__ float kg_s[256];
    __shared__ float Vs[64 * 64];
    __shared__ float smin[8], smax[8];

    int rest = blockIdx.x;
    int tid = threadIdx.x;
    int i = tid >> 1, th = tid & 1;

    if (tid < 256) {
        kg_s[tid] = g_kg[(size_t)rest * 256 + tid];
        float kmin = kg_s[tid], kmax = kmin;
        #pragma unroll
        for (int o = 16; o; o >>= 1) {
            kmin = fminf(kmin, __shfl_xor_sync(0xffffffffu, kmin, o));
            kmax = fmaxf(kmax, __shfl_xor_sync(0xffffffffu, kmax, o));
        }
        if ((tid & 31) == 0) { smin[tid >> 5] = kmin; smax[tid >> 5] = kmax; }
    }
    __syncthreads();
    float kmin = smin[0], kmax = smax[0];
    #pragma unroll
    for (int w = 1; w < 8; w++) { kmin = fminf(kmin, smin[w]); kmax = fmaxf(kmax, smax[w]); }

    float qgi = g_qg[(size_t)rest * 256 + i];
    float m = (qgi >= 0.f) ? qgi * kmax : qgi * kmin;   // exact row max

    float acc[32];
    #pragma unroll
    for (int t = 0; t < 32; t++) acc[t] = 0.f;
    float Z = 0.f;

    const float* Vbase = PTR_V;
    for (int jc = 0; jc < 4; jc++) {
        __syncthreads();
        const float4* vsrc = (const float4*)(Vbase + ((size_t)rest * 256 + jc * 64) * 64);
        float4* vdst = (float4*)Vs;
        #pragma unroll
        for (int u = 0; u < 2; u++) vdst[tid + u * 512] = vsrc[tid + u * 512];
        __syncthreads();
        #pragma unroll 2
        for (int j = 0; j < 64; j++) {
            float e = __expf(qgi * kg_s[jc * 64 + j] - m);
            Z += e;
            const float4* vr = (const float4*)(Vs + j * 64 + th * 32);
            #pragma unroll
            for (int t = 0; t < 8; t++) {
                float4 vv = vr[t];
                acc[t * 4 + 0] += e * vv.x;
                acc[t * 4 + 1] += e * vv.y;
                acc[t * 4 + 2] += e * vv.z;
                acc[t * 4 + 3] += e * vv.w;
            }
        }
    }
    float inv = 1.f / Z;
    float4* od = (float4*)(PTR_ATTN + ((size_t)rest * 256 + i) * 64 + th * 32);
    #pragma unroll
    for (int t = 0; t < 8; t++)
        od[t] = make_float4(acc[t * 4] * inv, acc[t * 4 + 1] * inv,
                            acc[t * 4 + 2] * inv, acc[t * 4 + 3] * inv);
}

// ---------------------------------------------------------------------------
// Kernel 4: proj via bf16 mma + window reverse + residual -> y (S0).
// Block = (sb, window-pair): M=128, N=128, K=128.
// ---------------------------------------------------------------------------
__global__ __launch_bounds__(256, 1) void k_proj_mma(
    const float* __restrict__ x, const float* __restrict__ proj_b_)
{
    extern __shared__ char smc[];
    __nv_bfloat16* Asm = (__nv_bfloat16*)smc;          // [128][264]
    __nv_bfloat16* Bsm = Asm + 128 * TSTRIDE;
    uint32_t sA = smem_u32(Asm), sB = smem_u32(Bsm);

    int tid = threadIdx.x, wid = tid >> 5, lane = tid & 31;
    int wm = wid >> 1, wn = wid & 1;
    int blk = blockIdx.x;
    int wp = blk & 127, sb = blk >> 7;
    int s = sb >> 3, b = sb & 7;

    // gather A[row = w2*64+pos][c] <- attn[(sb*128+c)*256 + 2wp+w2][pos], bf16
    #pragma unroll
    for (int rep = 0; rep < 4; rep++) {
        int runid = rep * 64 + (tid >> 2);    // 0..255 = (c, w2)
        int c = runid >> 1, w2 = runid & 1;
        int quarter = tid & 3;
        const float4* src = (const float4*)(PTR_ATTN +
            ((size_t)(sb * 128 + c) * 256 + wp * 2 + w2) * 64) + quarter * 4;
        #pragma unroll
        for (int u = 0; u < 4; u++) {
            float4 v = src[u];
            int row = w2 * 64 + quarter * 16 + u * 4;
            Asm[(row + 0) * TSTRIDE + c] = __float2bfloat16(v.x);
            Asm[(row + 1) * TSTRIDE + c] = __float2bfloat16(v.y);
            Asm[(row + 2) * TSTRIDE + c] = __float2bfloat16(v.z);
            Asm[(row + 3) * TSTRIDE + c] = __float2bfloat16(v.w);
        }
    }
    // load B (proj weights bf16): Bsm[n][k]
    {
        int n = tid >> 1, half = tid & 1;
        const uint4* ws = (const uint4*)(g_wpb + n * 128 + half * 64);
        uint4* bd = (uint4*)(Bsm + n * TSTRIDE + half * 64);
        #pragma unroll
        for (int u = 0; u < 8; u++) bd[u] = ws[u];
    }
    __syncthreads();

    float c[2][8][4];
    #pragma unroll
    for (int i = 0; i < 2; i++)
        #pragma unroll
        for (int j = 0; j < 8; j++)
            #pragma unroll
            for (int k = 0; k < 4; k++) c[i][j][k] = 0.f;

    mma_tile_bf16<128>(sA, sB, lane, wm, wn, c);
    __syncthreads();

    // stage T[token][n]
    float* T = (float*)smc;   // [128][132]
    #pragma unroll
    for (int mi = 0; mi < 2; mi++)
        #pragma unroll
        for (int n8 = 0; n8 < 8; n8++) {
            int rt = wm * 32 + mi * 16 + (lane >> 2);
            int cn = wn * 64 + n8 * 8 + (lane & 3) * 2;
            T[rt * 132 + cn]           = c[mi][n8][0];
            T[rt * 132 + cn + 1]       = c[mi][n8][1];
            T[(rt + 8) * 132 + cn]     = c[mi][n8][2];
            T[(rt + 8) * 132 + cn + 1] = c[mi][n8][3];
        }
    __syncthreads();

    // epilogue: y = x + proj + bias, window-reverse (+roll back)
    int r = tid >> 1, half = tid & 1;
    int w2 = r >> 6, p = r & 63;
    int win = wp * 2 + w2;
    int wy = win >> 4, wx = win & 15;
    int py = p >> 3, px = p & 7;
    int hh = wy * 8 + py, ww = wx * 8 + px;
    if (s) { hh = (hh + 4) & 127; ww = (ww + 4) & 127; }
    size_t base = ((size_t)(b * 16384 + hh * 128 + ww)) * 256 + s * 128 + half * 64;
    const float* trow = T + r * 132 + half * 64;
    #pragma unroll
    for (int u = 0; u < 16; u++) {
        float4 xv = *(const float4*)(x + base + u * 4);
        float4 pb = *(const float4*)(proj_b_ + half * 64 + u * 4);
        float4 o;
        o.x = trow[u * 4 + 0] + pb.x + xv.x;
        o.y = trow[u * 4 + 1] + pb.y + xv.y;
        o.z = trow[u * 4 + 2] + pb.z + xv.z;
        o.w = trow[u * 4 + 3] + pb.w + xv.w;
        *(float4*)(PTR_Y + base + u * 4) = o;
    }
}

// ---------------------------------------------------------------------------
// Kernel 5: LN2 -> bf16 Yn (token-major) in S3.
// ---------------------------------------------------------------------------
__global__ __launch_bounds__(256) void k_ln2(
    const float* __restrict__ n2g, const float* __restrict__ n2b)
{
    int token = blockIdx.x * 64 + (threadIdx.x >> 2);
    int q = threadIdx.x & 3;
    const float* yrow = PTR_Y + (size_t)token * 256;
    const float4* yr4 = (const float4*)yrow + q * 16;
    float sum = 0.f, sq = 0.f;
    #pragma unroll
    for (int i = 0; i < 16; i++) {
        float4 v = yr4[i];
        sum += v.x + v.y + v.z + v.w;
        sq  += v.x * v.x + v.y * v.y + v.z * v.z + v.w * v.w;
    }
    sum += __shfl_xor_sync(0xffffffffu, sum, 1);
    sum += __shfl_xor_sync(0xffffffffu, sum, 2);
    sq  += __shfl_xor_sync(0xffffffffu, sq, 1);
    sq  += __shfl_xor_sync(0xffffffffu, sq, 2);
    float mean = sum * (1.f / 256.f);
    float rstd = rsqrtf(sq * (1.f / 256.f) - mean * mean + 1e-5f);

    const float4* ys = (const float4*)(yrow + q * 64);
    const float4* gs = (const float4*)(n2g + q * 64);
    const float4* bs = (const float4*)(n2b + q * 64);
    uint32_t* dst = (uint32_t*)(PTR_YN + (size_t)token * 256 + q * 64);
    #pragma unroll
    for (int i = 0; i < 16; i++) {
        float4 v = ys[i], g = gs[i], b = bs[i];
        float o0 = (v.x - mean) * rstd * g.x + b.x;
        float o1 = (v.y - mean) * rstd * g.y + b.y;
        float o2 = (v.z - mean) * rstd * g.z + b.z;
        float o3 = (v.w - mean) * rstd * g.w + b.w;
        uint32_t u0 = (uint32_t)__bfloat16_as_ushort(__float2bfloat16(o0))
                    | ((uint32_t)__bfloat16_as_ushort(__float2bfloat16(o1)) << 16);
        uint32_t u1 = (uint32_t)__bfloat16_as_ushort(__float2bfloat16(o2))
                    | ((uint32_t)__bfloat16_as_ushort(__float2bfloat16(o3)) << 16);
        dst[i * 2 + 0] = u0;
        dst[i * 2 + 1] = u1;
    }
}

// ---------------------------------------------------------------------------
// Kernel 5b: convert fc1/fc2/proj weights to bf16.
// ---------------------------------------------------------------------------
__global__ __launch_bounds__(256) void k_cvt(
    const float* __restrict__ w1, const float* __restrict__ w2, const float* __restrict__ wp)
{
    int i = blockIdx.x * 256 + threadIdx.x;
    if (i < 131072)      g_w1b[i] = __float2bfloat16(w1[i]);
    else if (i < 196608) g_w2b[i - 131072] = __float2bfloat16(w2[i - 131072]);
    else if (i < 212992) g_wpb[i - 196608] = __float2bfloat16(wp[i - 196608]);
}

// ---------------------------------------------------------------------------
// Kernel 6: fc1 via mma.sync bf16. Tile M=128, N=128, K=256.
// Grid (1024 M-tiles, 4 N-tiles). Epilogue: +bias, fp32 NCHW into S1+S2.
// ---------------------------------------------------------------------------
__global__ __launch_bounds__(256, 1) void k_fc1_mma(const float* __restrict__ fc1_b_)
{
    extern __shared__ char smc[];
    __nv_bfloat16* Asm = (__nv_bfloat16*)smc;
    __nv_bfloat16* Bsm = Asm + 128 * TSTRIDE;
    uint32_t sA = smem_u32(Asm), sB = smem_u32(Bsm);

    int tid = threadIdx.x, wid = tid >> 5, lane = tid & 31;
    int wm = wid >> 1, wn = wid & 1;
    int mt = blockIdx.x, nt = blockIdx.y;

    const __nv_bfloat16* Asrc = PTR_YN + (size_t)mt * 128 * 256;
    const __nv_bfloat16* Bsrc = g_w1b + (size_t)nt * 128 * 256;
    for (int idx = tid; idx < 4096; idx += 256) {
        int row = idx >> 5, c8 = (idx & 31) << 3;
        *(uint4*)(Asm + row * TSTRIDE + c8) = *(const uint4*)(Asrc + row * 256 + c8);
        *(uint4*)(Bsm + row * TSTRIDE + c8) = *(const uint4*)(Bsrc + row * 256 + c8);
    }
    __syncthreads();

    float c[2][8][4];
    #pragma unroll
    for (int i = 0; i < 2; i++)
        #pragma unroll
        for (int j = 0; j < 8; j++)
            #pragma unroll
            for (int k = 0; k < 4; k++) c[i][j][k] = 0.f;

    mma_tile_bf16<256>(sA, sB, lane, wm, wn, c);
    __syncthreads();

    float* T = (float*)smc;   // [128 n][132 token]
    #pragma unroll
    for (int mi = 0; mi < 2; mi++)
        #pragma unroll
        for (int n8 = 0; n8 < 8; n8++) {
            int rt = wm * 32 + mi * 16 + (lane >> 2);
            int cn = wn * 64 + n8 * 8 + (lane & 3) * 2;
            T[cn * 132 + rt]           = c[mi][n8][0];
            T[(cn + 1) * 132 + rt]     = c[mi][n8][1];
            T[cn * 132 + rt + 8]       = c[mi][n8][2];
            T[(cn + 1) * 132 + rt + 8] = c[mi][n8][3];
        }
    __syncthreads();

    int token0 = mt * 128;
    int b = token0 >> 14;
    int hw0 = token0 & 16383;
    int n = tid >> 1, half = tid & 1;
    float bias = fc1_b_[nt * 128 + n];
    float* dst = PTR_FC1 + ((size_t)(b * 512 + nt * 128 + n)) * 16384 + hw0 + half * 64;
    const float* trow = T + n * 132 + half * 64;
    #pragma unroll
    for (int u = 0; u < 16; u++) {
        float4 o = make_float4(trow[u * 4 + 0] + bias, trow[u * 4 + 1] + bias,
                               trow[u * 4 + 2] + bias, trow[u * 4 + 3] + bias);
        *(float4*)(dst + u * 4) = o;
    }
}

// ---------------------------------------------------------------------------
// Kernel 7: depthwise 3x3 conv + gate (fp32 NCHW, unchanged).
// ---------------------------------------------------------------------------
__global__ __launch_bounds__(256) void k_dwgate(
    const float* __restrict__ dw_w, const float* __restrict__ dw_b)
{
    __shared__ float in0[6][130];
    __shared__ float in1[6][130];
    __shared__ float wsm[2][9];
    __shared__ float bsm[2];

    int y0 = blockIdx.x * 4;
    int c  = blockIdx.y;
    int b  = blockIdx.z;
    int tid = threadIdx.x;

    if (tid < 18) { int ch = tid / 9, k = tid - ch * 9; wsm[ch][k] = dw_w[(size_t)(c + ch * 256) * 9 + k]; }
    if (tid < 2) bsm[tid] = dw_b[c + tid * 256];

    for (int e = tid; e < 2 * 6 * 130; e += 256) {
        int ch = e / 780;
        int rem = e - ch * 780;
        int rr = rem / 130;
        int cc = rem - rr * 130;
        int gy = y0 - 1 + rr, gx = cc - 1;
        float v = 0.f;
        if (gy >= 0 && gy < 128 && gx >= 0 && gx < 128)
            v = PTR_FC1[(size_t)(b * 512 + c + ch * 256) * 16384 + gy * 128 + gx];
        if (ch) in1[rr][cc] = v; else in0[rr][cc] = v;
    }
    __syncthreads();

    #pragma unroll
    for (int k = 0; k < 2; k++) {
        int o = tid + k * 256;
        int yy = o >> 7, xx = o & 127;
        float c0 = bsm[0], c1 = bsm[1];
        #pragma unroll
        for (int ky = 0; ky < 3; ky++)
            #pragma unroll
            for (int kx = 0; kx < 3; kx++) {
                c0 += wsm[0][ky * 3 + kx] * in0[yy + ky][xx + kx];
                c1 += wsm[1][ky * 3 + kx] * in1[yy + ky][xx + kx];
            }
        PTR_GATE[(size_t)(b * 256 + c) * 16384 + (y0 + yy) * 128 + xx] = c0 * c1;
    }
}

// ---------------------------------------------------------------------------
// Kernel 8: gate NCHW fp32 -> token-major bf16 (gate_t in S1).
// ---------------------------------------------------------------------------
__global__ __launch_bounds__(256) void k_tr()
{
    __shared__ float t[32][33];
    int hw0 = blockIdx.x * 32, c0 = blockIdx.y * 32, b = blockIdx.z;
    int tx = threadIdx.x & 31, ty = threadIdx.x >> 5;
    #pragma unroll
    for (int i = 0; i < 4; i++) {
        int c = c0 + ty + i * 8;
        t[ty + i * 8][tx] = PTR_GATE[((size_t)(b * 256 + c)) * 16384 + hw0 + tx];
    }
    __syncthreads();
    #pragma unroll
    for (int i = 0; i < 4; i++) {
        int row = ty + i * 8;
        PTR_GT[((size_t)(b * 16384 + hw0 + row)) * 256 + c0 + tx] = __float2bfloat16(t[tx][row]);
    }
}

// ---------------------------------------------------------------------------
// Kernel 9: fc2 via mma.sync bf16. Tile M=128, N=128, K=256. Grid (1024, 2).
// Epilogue: +bias +residual(Y) -> d_out (token-major).
// ---------------------------------------------------------------------------
__global__ __launch_bounds__(256, 1) void k_fc2_mma(
    const float* __restrict__ fc2_b_, float* __restrict__ out)
{
    extern __shared__ char smc[];
    __nv_bfloat16* Asm = (__nv_bfloat16*)smc;
    __nv_bfloat16* Bsm = Asm + 128 * TSTRIDE;
    uint32_t sA = smem_u32(Asm), sB = smem_u32(Bsm);

    int tid = threadIdx.x, wid = tid >> 5, lane = tid & 31;
    int wm = wid >> 1, wn = wid & 1;
    int mt = blockIdx.x, nt = blockIdx.y;

    const __nv_bfloat16* Asrc = PTR_GT + (size_t)mt * 128 * 256;
    const __nv_bfloat16* Bsrc = g_w2b + (size_t)nt * 128 * 256;
    for (int idx = tid; idx < 4096; idx += 256) {
        int row = idx >> 5, c8 = (idx & 31) << 3;
        *(uint4*)(Asm + row * TSTRIDE + c8) = *(const uint4*)(Asrc + row * 256 + c8);
        *(uint4*)(Bsm + row * TSTRIDE + c8) = *(const uint4*)(Bsrc + row * 256 + c8);
    }
    __syncthreads();

    float c[2][8][4];
    #pragma unroll
    for (int i = 0; i < 2; i++)
        #pragma unroll
        for (int j = 0; j < 8; j++)
            #pragma unroll
            for (int k = 0; k < 4; k++) c[i][j][k] = 0.f;

    mma_tile_bf16<256>(sA, sB, lane, wm, wn, c);
    __syncthreads();

    float* T = (float*)smc;   // [128 token][132 n]
    #pragma unroll
    for (int mi = 0; mi < 2; mi++)
        #pragma unroll
        for (int n8 = 0; n8 < 8; n8++) {
            int rt = wm * 32 + mi * 16 + (lane >> 2);
            int cn = wn * 64 + n8 * 8 + (lane & 3) * 2;
            T[rt * 132 + cn]           = c[mi][n8][0];
            T[rt * 132 + cn + 1]       = c[mi][n8][1];
            T[(rt + 8) * 132 + cn]     = c[mi][n8][2];
            T[(rt + 8) * 132 + cn + 1] = c[mi][n8][3];
        }
    __syncthreads();

    size_t token0 = (size_t)mt * 128;
    int m = tid >> 1, half = tid & 1;
    int n0 = nt * 128 + half * 64;
    size_t base = (token0 + m) * 256 + n0;
    const float* trow = T + m * 132 + half * 64;
    #pragma unroll
    for (int u = 0; u < 16; u++) {
        float4 y = *(const float4*)(PTR_Y + base + u * 4);
        float4 o;
        o.x = trow[u * 4 + 0] + fc2_b_[n0 + u * 4 + 0] + y.x;
        o.y = trow[u * 4 + 1] + fc2_b_[n0 + u * 4 + 1] + y.y;
        o.z = trow[u * 4 + 2] + fc2_b_[n0 + u * 4 + 2] + y.z;
        o.w = trow[u * 4 + 3] + fc2_b_[n0 + u * 4 + 3] + y.w;
        *(float4*)(out + base + u * 4) = o;
    }
}

// ---------------------------------------------------------------------------
extern "C" void kernel_launch(void* const* d_in, const int* in_sizes, int n_in,
                              void* d_out, int out_size)
{
    const float* x      = (const float*)d_in[0];
    const float* n1g    = (const float*)d_in[1];
    const float* n1b    = (const float*)d_in[2];
    const float* qkv_w  = (const float*)d_in[3];
    const float* qkv_b  = (const float*)d_in[4];
    const float* proj_w = (const float*)d_in[5];
    const float* proj_b = (const float*)d_in[6];
    const float* n2g    = (const float*)d_in[7];
    const float* n2b    = (const float*)d_in[8];
    const float* fc1_w  = (const float*)d_in[9];
    const float* fc1_b  = (const float*)d_in[10];
    const float* dw_w   = (const float*)d_in[11];
    const float* dw_b   = (const float*)d_in[12];
    const float* fc2_w  = (const float*)d_in[13];
    const float* fc2_b  = (const float*)d_in[14];
    float* out = (float*)d_out;

    cudaFuncSetAttribute(k_qkv_mma,  cudaFuncAttributeMaxDynamicSharedMemorySize, 135168);
    cudaFuncSetAttribute(k_proj_mma, cudaFuncAttributeMaxDynamicSharedMemorySize, 135168);
    cudaFuncSetAttribute(k_fc1_mma,  cudaFuncAttributeMaxDynamicSharedMemorySize, 135168);
    cudaFuncSetAttribute(k_fc2_mma,  cudaFuncAttributeMaxDynamicSharedMemorySize, 135168);

    k_cvt<<<832, 256>>>(fc1_w, fc2_w, proj_w);
    k_qkv_mma<<<2048, 256, 135168>>>(x, n1g, n1b, qkv_w, qkv_b);
    k_grad<<<dim3(2048, 2), 256>>>();
    k_attn<<<2048, 512>>>();
    k_proj_mma<<<2048, 256, 135168>>>(x, proj_b);
    k_ln2<<<2048, 256>>>(n2g, n2b);
    k_fc1_mma<<<dim3(1024, 4), 256, 135168>>>(fc1_b);
    k_dwgate<<<dim3(32, 256, 8), 256>>>(dw_w, dw_b);
    k_tr<<<dim3(512, 8, 8), 256>>>();
    k_fc2_mma<<<dim3(1024, 2), 256, 135168>>>(fc2_b, out);
}

// round 10
// speedup vs baseline: 1.5453x; 1.0739x over previous
#include <cuda_runtime.h>
#include <cuda_bf16.h>
#include <cstdint>

// ---------------------------------------------------------------------------
// B=8, H=W=128, L=16384, DIM=256, C_ATTN=128, WS=8, SHIFT=4,
// HEADS=4, HD=32, HIDDEN=512, 256 windows x 64 tokens, 2 shift branches.
//
// Scratch slots (128MB each):
//   S0: Q  -> y (residual, live to end)
//   S1: K  -> fc1 out (lower)  -> gate_t bf16 (after dwgate)
//   S2: V  -> fc1 out (upper)
//   S3: attn-out -> Yn bf16 (ln2 out) -> gate fp32 NCHW (dwgate out)
// ---------------------------------------------------------------------------

#define SLOT 33554432
__device__ float g_scratch[4 * SLOT];
__device__ float g_qg[524288];
__device__ float g_kg[524288];
__device__ __nv_bfloat16 g_w1b[512 * 256];
__device__ __nv_bfloat16 g_w2b[256 * 256];
__device__ __nv_bfloat16 g_wpb[128 * 128];

#define PTR_Q    (g_scratch)
#define PTR_K    (g_scratch + SLOT)
#define PTR_V    (g_scratch + 2 * SLOT)
#define PTR_ATTN (g_scratch + 3 * SLOT)
#define PTR_Y    (g_scratch)
#define PTR_FC1  (g_scratch + SLOT)
#define PTR_GATE (g_scratch + 3 * SLOT)
#define PTR_YN   ((__nv_bfloat16*)(g_scratch + 3 * SLOT))
#define PTR_GT   ((__nv_bfloat16*)(g_scratch + SLOT))

// ------------------------------ helpers ------------------------------------
__device__ __forceinline__ uint32_t smem_u32(const void* p) {
    uint32_t a;
    asm("{ .reg .u64 t; cvta.to.shared.u64 t, %1; cvt.u32.u64 %0, t; }" : "=r"(a) : "l"(p));
    return a;
}
__device__ __forceinline__ void ldmx4(uint32_t* r, uint32_t addr) {
    asm volatile("ldmatrix.sync.aligned.m8n8.x4.shared.b16 {%0,%1,%2,%3}, [%4];"
        : "=r"(r[0]), "=r"(r[1]), "=r"(r[2]), "=r"(r[3]) : "r"(addr));
}
__device__ __forceinline__ void mma16816(float* c, const uint32_t* a, uint32_t b0, uint32_t b1) {
    asm volatile("mma.sync.aligned.m16n8k16.row.col.f32.bf16.bf16.f32 "
        "{%0,%1,%2,%3}, {%4,%5,%6,%7}, {%8,%9}, {%0,%1,%2,%3};"
        : "+f"(c[0]), "+f"(c[1]), "+f"(c[2]), "+f"(c[3])
        : "r"(a[0]), "r"(a[1]), "r"(a[2]), "r"(a[3]), "r"(b0), "r"(b1));
}
__device__ __forceinline__ uint32_t pack_bf16x2(float lo, float hi) {
    return (uint32_t)__bfloat16_as_ushort(__float2bfloat16(lo))
         | ((uint32_t)__bfloat16_as_ushort(__float2bfloat16(hi)) << 16);
}

// bf16 mma core over [128 rows] x [128 cols] warp-tiled 4x2; row stride in
// elements is a template param (pad chosen so ldmatrix is bank-conflict-free).
#define TSTRIDE 264
#define TSTRB   (TSTRIDE * 2)

template<int KMAX, int STRIDE>
__device__ __forceinline__ void mma_tile_bf16(
    uint32_t sA, uint32_t sB, int lane, int wm, int wn, float (&c)[2][8][4])
{
    const int SB = STRIDE * 2;
    uint32_t aRowB = sA + (uint32_t)(wm * 32 + (lane & 15)) * SB + (uint32_t)((lane >> 4) << 4);
    uint32_t bRowB = sB + (uint32_t)(wn * 64 + (lane & 7) + ((lane >> 4) << 3)) * SB
                   + (uint32_t)(((lane >> 3) & 1) << 4);
    #pragma unroll
    for (int k0 = 0; k0 < KMAX; k0 += 16) {
        uint32_t a[2][4];
        #pragma unroll
        for (int mi = 0; mi < 2; mi++)
            ldmx4(a[mi], aRowB + (uint32_t)(mi * 16) * SB + k0 * 2);
        uint32_t bf[4][4];
        #pragma unroll
        for (int nf = 0; nf < 4; nf++)
            ldmx4(bf[nf], bRowB + (uint32_t)(nf * 16) * SB + k0 * 2);
        #pragma unroll
        for (int mi = 0; mi < 2; mi++)
            #pragma unroll
            for (int n8 = 0; n8 < 8; n8++)
                mma16816(c[mi][n8], a[mi], bf[n8 >> 1][(n8 & 1) * 2], bf[n8 >> 1][(n8 & 1) * 2 + 1]);
    }
}

// ---------------------------------------------------------------------------
// Kernel 1: LN1 + window partition (+roll) + QKV GEMM via bf16 hi/lo split
// mma (3 passes: hi*hi + hi*lo + lo*hi; residual ~4e-6 relative).
// Block = (sb, window-pair): M=128 tokens, N=128 x 3 chunks (q,k,v), K=128.
// smem: Ahi/Alo/Bhi/Blo bf16 [128][136] = 139264 B; T fp32 aliases Bhi+Blo.
// ---------------------------------------------------------------------------
#define QSTRIDE 136
__global__ __launch_bounds__(256, 1) void k_qkv_mma(
    const float* __restrict__ x, const float* __restrict__ n1g, const float* __restrict__ n1b,
    const float* __restrict__ qkv_w, const float* __restrict__ qkv_b)
{
    extern __shared__ char smc[];
    const uint32_t TILE = 128 * QSTRIDE * 2;   // 34816 B
    __nv_bfloat16* Ahi = (__nv_bfloat16*)smc;
    __nv_bfloat16* Alo = (__nv_bfloat16*)(smc + TILE);
    __nv_bfloat16* Bhi = (__nv_bfloat16*)(smc + 2 * TILE);
    __nv_bfloat16* Blo = (__nv_bfloat16*)(smc + 3 * TILE);
    float* T = (float*)(smc + 2 * TILE);       // [128][132], overlaps Bhi/Blo
    uint32_t sAhi = smem_u32(Ahi), sAlo = smem_u32(Alo);
    uint32_t sBhi = smem_u32(Bhi), sBlo = smem_u32(Blo);

    int tid = threadIdx.x, wid = tid >> 5, lane = tid & 31;
    int wm = wid >> 1, wn = wid & 1;
    int blk = blockIdx.x;
    int wp = blk & 127, sb = blk >> 7;
    int s = sb >> 3, b = sb & 7;

    // ---- LN1 for 128 tokens (2 windows), branch-s channels, hi/lo split ----
    {
        int r = tid >> 1, q = tid & 1;
        int w2 = r >> 6, p = r & 63;
        int win = wp * 2 + w2;
        int wy = win >> 4, wx = win & 15;
        int py = p >> 3, px = p & 7;
        int hh = wy * 8 + py, ww = wx * 8 + px;
        if (s) { hh = (hh + 4) & 127; ww = (ww + 4) & 127; }
        const float* xrow = x + ((size_t)(b * 16384 + hh * 128 + ww)) * 256;
        const float4* xr4 = (const float4*)xrow + q * 32;
        float sum = 0.f, sq = 0.f;
        #pragma unroll
        for (int i = 0; i < 32; i++) {
            float4 v = xr4[i];
            sum += v.x + v.y + v.z + v.w;
            sq  += v.x * v.x + v.y * v.y + v.z * v.z + v.w * v.w;
        }
        sum += __shfl_xor_sync(0xffffffffu, sum, 1);
        sq  += __shfl_xor_sync(0xffffffffu, sq, 1);
        float mean = sum * (1.f / 256.f);
        float rstd = rsqrtf(sq * (1.f / 256.f) - mean * mean + 1e-5f);

        const float4* xb = (const float4*)(xrow + s * 128 + q * 64);
        const float4* gg = (const float4*)(n1g + s * 128 + q * 64);
        const float4* bb = (const float4*)(n1b + s * 128 + q * 64);
        uint32_t* ah = (uint32_t*)(Ahi + r * QSTRIDE + q * 64);
        uint32_t* al = (uint32_t*)(Alo + r * QSTRIDE + q * 64);
        #pragma unroll
        for (int i = 0; i < 16; i++) {
            float4 v = xb[i], g = gg[i], bv = bb[i];
            float o0 = (v.x - mean) * rstd * g.x + bv.x;
            float o1 = (v.y - mean) * rstd * g.y + bv.y;
            float o2 = (v.z - mean) * rstd * g.z + bv.z;
            float o3 = (v.w - mean) * rstd * g.w + bv.w;
            __nv_bfloat16 h0 = __float2bfloat16(o0), h1 = __float2bfloat16(o1);
            __nv_bfloat16 h2 = __float2bfloat16(o2), h3 = __float2bfloat16(o3);
            ah[i * 2 + 0] = (uint32_t)__bfloat16_as_ushort(h0)
                          | ((uint32_t)__bfloat16_as_ushort(h1) << 16);
            ah[i * 2 + 1] = (uint32_t)__bfloat16_as_ushort(h2)
                          | ((uint32_t)__bfloat16_as_ushort(h3) << 16);
            al[i * 2 + 0] = pack_bf16x2(o0 - __bfloat162float(h0), o1 - __bfloat162float(h1));
            al[i * 2 + 1] = pack_bf16x2(o2 - __bfloat162float(h2), o3 - __bfloat162float(h3));
        }
    }

    for (int chunk = 0; chunk < 3; chunk++) {
        __syncthreads();   // A ready (chunk 0) / T-in-B-region reads done (chunk>0)
        {
            int n = tid >> 1, half = tid & 1;
            const float4* src = (const float4*)(qkv_w + (size_t)(chunk * 128 + n) * 128 + half * 64);
            uint32_t* bh = (uint32_t*)(Bhi + n * QSTRIDE + half * 64);
            uint32_t* bl = (uint32_t*)(Blo + n * QSTRIDE + half * 64);
            #pragma unroll
            for (int i = 0; i < 16; i++) {
                float4 v = src[i];
                __nv_bfloat16 h0 = __float2bfloat16(v.x), h1 = __float2bfloat16(v.y);
                __nv_bfloat16 h2 = __float2bfloat16(v.z), h3 = __float2bfloat16(v.w);
                bh[i * 2 + 0] = (uint32_t)__bfloat16_as_ushort(h0)
                              | ((uint32_t)__bfloat16_as_ushort(h1) << 16);
                bh[i * 2 + 1] = (uint32_t)__bfloat16_as_ushort(h2)
                              | ((uint32_t)__bfloat16_as_ushort(h3) << 16);
                bl[i * 2 + 0] = pack_bf16x2(v.x - __bfloat162float(h0), v.y - __bfloat162float(h1));
                bl[i * 2 + 1] = pack_bf16x2(v.z - __bfloat162float(h2), v.w - __bfloat162float(h3));
            }
        }
        __syncthreads();

        float c[2][8][4];
        #pragma unroll
        for (int i = 0; i < 2; i++)
            #pragma unroll
            for (int j = 0; j < 8; j++)
                #pragma unroll
                for (int k = 0; k < 4; k++) c[i][j][k] = 0.f;

        mma_tile_bf16<128, QSTRIDE>(sAhi, sBhi, lane, wm, wn, c);
        mma_tile_bf16<128, QSTRIDE>(sAhi, sBlo, lane, wm, wn, c);
        mma_tile_bf16<128, QSTRIDE>(sAlo, sBhi, lane, wm, wn, c);
        __syncthreads();   // all mma reads of Bhi/Blo done before T overwrites

        // stage T[n][token]
        #pragma unroll
        for (int mi = 0; mi < 2; mi++)
            #pragma unroll
            for (int n8 = 0; n8 < 8; n8++) {
                int rt = wm * 32 + mi * 16 + (lane >> 2);
                int cn = wn * 64 + n8 * 8 + (lane & 3) * 2;
                T[cn * 132 + rt]           = c[mi][n8][0];
                T[(cn + 1) * 132 + rt]     = c[mi][n8][1];
                T[cn * 132 + rt + 8]       = c[mi][n8][2];
                T[(cn + 1) * 132 + rt + 8] = c[mi][n8][3];
            }
        __syncthreads();

        float* dst = (chunk == 0) ? PTR_Q : (chunk == 1) ? PTR_K : PTR_V;
        int rr = tid >> 1, half = tid & 1;
        float bias = qkv_b[chunk * 128 + rr];
        float* drow = dst + ((size_t)(sb * 128 + rr) * 256 + wp * 2) * 64 + half * 64;
        const float* trow = T + rr * 132 + half * 64;
        #pragma unroll
        for (int u = 0; u < 16; u++) {
            float4 o = make_float4(trow[u * 4 + 0] + bias, trow[u * 4 + 1] + bias,
                                   trow[u * 4 + 2] + bias, trow[u * 4 + 3] + bias);
            *(float4*)(drow + u * 4) = o;
        }
    }
}

// ---------------------------------------------------------------------------
// Kernel 2: finite-difference gradient scores (524288 items, grid (2048,2)).
// ---------------------------------------------------------------------------
__global__ __launch_bounds__(256) void k_grad()
{
    int idx = blockIdx.x * 256 + threadIdx.x;
    const float* src = blockIdx.y ? PTR_K : PTR_Q;
    float*       dst = blockIdx.y ? g_kg : g_qg;
    float scale = blockIdx.y ? 1.f : 0.17677669529663687f;

    float v[64];
    const float4* p = (const float4*)(src + (size_t)idx * 64);
    #pragma unroll
    for (int i = 0; i < 16; i++) {
        float4 t = p[i];
        v[i * 4 + 0] = t.x; v[i * 4 + 1] = t.y; v[i * 4 + 2] = t.z; v[i * 4 + 3] = t.w;
    }
    float sc = 0.f;
    #pragma unroll
    for (int py = 0; py < 8; py++)
        #pragma unroll
        for (int px = 0; px < 8; px++) {
            float t = v[py * 8 + px];
            float gx = px ? (t - v[py * 8 + px - 1]) : t;
            float gy = py ? (t - v[(py - 1) * 8 + px]) : t;
            sc += fabsf(gx) + fabsf(gy);
        }
    dst[idx] = sc * scale;
}

// ---------------------------------------------------------------------------
// Kernel 3: inter-window rank-1 softmax attention (fp32).
// 512 threads: thread = (dest window i = tid>>1, t-half th = tid&1), acc[32].
// minBlocks=2 caps regs at 64 -> 2 blocks/SM -> 32 warps (was 16).
// ---------------------------------------------------------------------------
__global__ __launch_bounds__(512, 2) void k_attn()
{
    __shared__ float kg_s[256];
    __shared__ float Vs[64 * 64];
    __shared__ float smin[8], smax[8];

    int rest = blockIdx.x;
    int tid = threadIdx.x;
    int i = tid >> 1, th = tid & 1;

    if (tid < 256) {
        kg_s[tid] = g_kg[(size_t)rest * 256 + tid];
        float kmin = kg_s[tid], kmax = kmin;
        #pragma unroll
        for (int o = 16; o; o >>= 1) {
            kmin = fminf(kmin, __shfl_xor_sync(0xffffffffu, kmin, o));
            kmax = fmaxf(kmax, __shfl_xor_sync(0xffffffffu, kmax, o));
        }
        if ((tid & 31) == 0) { smin[tid >> 5] = kmin; smax[tid >> 5] = kmax; }
    }
    __syncthreads();
    float kmin = smin[0], kmax = smax[0];
    #pragma unroll
    for (int w = 1; w < 8; w++) { kmin = fminf(kmin, smin[w]); kmax = fmaxf(kmax, smax[w]); }

    float qgi = g_qg[(size_t)rest * 256 + i];
    float m = (qgi >= 0.f) ? qgi * kmax : qgi * kmin;   // exact row max

    float acc[32];
    #pragma unroll
    for (int t = 0; t < 32; t++) acc[t] = 0.f;
    float Z = 0.f;

    const float* Vbase = PTR_V;
    for (int jc = 0; jc < 4; jc++) {
        __syncthreads();
        const float4* vsrc = (const float4*)(Vbase + ((size_t)rest * 256 + jc * 64) * 64);
        float4* vdst = (float4*)Vs;
        #pragma unroll
        for (int u = 0; u < 2; u++) vdst[tid + u * 512] = vsrc[tid + u * 512];
        __syncthreads();
        #pragma unroll 2
        for (int j = 0; j < 64; j++) {
            float e = __expf(qgi * kg_s[jc * 64 + j] - m);
            Z += e;
            const float4* vr = (const float4*)(Vs + j * 64 + th * 32);
            #pragma unroll
            for (int t = 0; t < 8; t++) {
                float4 vv = vr[t];
                acc[t * 4 + 0] += e * vv.x;
                acc[t * 4 + 1] += e * vv.y;
                acc[t * 4 + 2] += e * vv.z;
                acc[t * 4 + 3] += e * vv.w;
            }
        }
    }
    float inv = 1.f / Z;
    float4* od = (float4*)(PTR_ATTN + ((size_t)rest * 256 + i) * 64 + th * 32);
    #pragma unroll
    for (int t = 0; t < 8; t++)
        od[t] = make_float4(acc[t * 4] * inv, acc[t * 4 + 1] * inv,
                            acc[t * 4 + 2] * inv, acc[t * 4 + 3] * inv);
}

// ---------------------------------------------------------------------------
// Kernel 4: proj via bf16 mma + window reverse + residual -> y (S0).
// Block = (sb, window-pair): M=128, N=128, K=128.
// ---------------------------------------------------------------------------
__global__ __launch_bounds__(256, 1) void k_proj_mma(
    const float* __restrict__ x, const float* __restrict__ proj_b_)
{
    extern __shared__ char smc[];
    __nv_bfloat16* Asm = (__nv_bfloat16*)smc;          // [128][264]
    __nv_bfloat16* Bsm = Asm + 128 * TSTRIDE;
    uint32_t sA = smem_u32(Asm), sB = smem_u32(Bsm);

    int tid = threadIdx.x, wid = tid >> 5, lane = tid & 31;
    int wm = wid >> 1, wn = wid & 1;
    int blk = blockIdx.x;
    int wp = blk & 127, sb = blk >> 7;
    int s = sb >> 3, b = sb & 7;

    // gather A[row = w2*64+pos][c] <- attn[(sb*128+c)*256 + 2wp+w2][pos], bf16
    #pragma unroll
    for (int rep = 0; rep < 4; rep++) {
        int runid = rep * 64 + (tid >> 2);    // 0..255 = (c, w2)
        int c = runid >> 1, w2 = runid & 1;
        int quarter = tid & 3;
        const float4* src = (const float4*)(PTR_ATTN +
            ((size_t)(sb * 128 + c) * 256 + wp * 2 + w2) * 64) + quarter * 4;
        #pragma unroll
        for (int u = 0; u < 4; u++) {
            float4 v = src[u];
            int row = w2 * 64 + quarter * 16 + u * 4;
            Asm[(row + 0) * TSTRIDE + c] = __float2bfloat16(v.x);
            Asm[(row + 1) * TSTRIDE + c] = __float2bfloat16(v.y);
            Asm[(row + 2) * TSTRIDE + c] = __float2bfloat16(v.z);
            Asm[(row + 3) * TSTRIDE + c] = __float2bfloat16(v.w);
        }
    }
    // load B (proj weights bf16): Bsm[n][k]
    {
        int n = tid >> 1, half = tid & 1;
        const uint4* ws = (const uint4*)(g_wpb + n * 128 + half * 64);
        uint4* bd = (uint4*)(Bsm + n * TSTRIDE + half * 64);
        #pragma unroll
        for (int u = 0; u < 8; u++) bd[u] = ws[u];
    }
    __syncthreads();

    float c[2][8][4];
    #pragma unroll
    for (int i = 0; i < 2; i++)
        #pragma unroll
        for (int j = 0; j < 8; j++)
            #pragma unroll
            for (int k = 0; k < 4; k++) c[i][j][k] = 0.f;

    mma_tile_bf16<128, TSTRIDE>(sA, sB, lane, wm, wn, c);
    __syncthreads();

    // stage T[token][n]
    float* T = (float*)smc;   // [128][132]
    #pragma unroll
    for (int mi = 0; mi < 2; mi++)
        #pragma unroll
        for (int n8 = 0; n8 < 8; n8++) {
            int rt = wm * 32 + mi * 16 + (lane >> 2);
            int cn = wn * 64 + n8 * 8 + (lane & 3) * 2;
            T[rt * 132 + cn]           = c[mi][n8][0];
            T[rt * 132 + cn + 1]       = c[mi][n8][1];
            T[(rt + 8) * 132 + cn]     = c[mi][n8][2];
            T[(rt + 8) * 132 + cn + 1] = c[mi][n8][3];
        }
    __syncthreads();

    // epilogue: y = x + proj + bias, window-reverse (+roll back)
    int r = tid >> 1, half = tid & 1;
    int w2 = r >> 6, p = r & 63;
    int win = wp * 2 + w2;
    int wy = win >> 4, wx = win & 15;
    int py = p >> 3, px = p & 7;
    int hh = wy * 8 + py, ww = wx * 8 + px;
    if (s) { hh = (hh + 4) & 127; ww = (ww + 4) & 127; }
    size_t base = ((size_t)(b * 16384 + hh * 128 + ww)) * 256 + s * 128 + half * 64;
    const float* trow = T + r * 132 + half * 64;
    #pragma unroll
    for (int u = 0; u < 16; u++) {
        float4 xv = *(const float4*)(x + base + u * 4);
        float4 pb = *(const float4*)(proj_b_ + half * 64 + u * 4);
        float4 o;
        o.x = trow[u * 4 + 0] + pb.x + xv.x;
        o.y = trow[u * 4 + 1] + pb.y + xv.y;
        o.z = trow[u * 4 + 2] + pb.z + xv.z;
        o.w = trow[u * 4 + 3] + pb.w + xv.w;
        *(float4*)(PTR_Y + base + u * 4) = o;
    }
}

// ---------------------------------------------------------------------------
// Kernel 5: LN2 -> bf16 Yn (token-major) in S3.
// ---------------------------------------------------------------------------
__global__ __launch_bounds__(256) void k_ln2(
    const float* __restrict__ n2g, const float* __restrict__ n2b)
{
    int token = blockIdx.x * 64 + (threadIdx.x >> 2);
    int q = threadIdx.x & 3;
    const float* yrow = PTR_Y + (size_t)token * 256;
    const float4* yr4 = (const float4*)yrow + q * 16;
    float sum = 0.f, sq = 0.f;
    #pragma unroll
    for (int i = 0; i < 16; i++) {
        float4 v = yr4[i];
        sum += v.x + v.y + v.z + v.w;
        sq  += v.x * v.x + v.y * v.y + v.z * v.z + v.w * v.w;
    }
    sum += __shfl_xor_sync(0xffffffffu, sum, 1);
    sum += __shfl_xor_sync(0xffffffffu, sum, 2);
    sq  += __shfl_xor_sync(0xffffffffu, sq, 1);
    sq  += __shfl_xor_sync(0xffffffffu, sq, 2);
    float mean = sum * (1.f / 256.f);
    float rstd = rsqrtf(sq * (1.f / 256.f) - mean * mean + 1e-5f);

    const float4* ys = (const float4*)(yrow + q * 64);
    const float4* gs = (const float4*)(n2g + q * 64);
    const float4* bs = (const float4*)(n2b + q * 64);
    uint32_t* dst = (uint32_t*)(PTR_YN + (size_t)token * 256 + q * 64);
    #pragma unroll
    for (int i = 0; i < 16; i++) {
        float4 v = ys[i], g = gs[i], b = bs[i];
        float o0 = (v.x - mean) * rstd * g.x + b.x;
        float o1 = (v.y - mean) * rstd * g.y + b.y;
        float o2 = (v.z - mean) * rstd * g.z + b.z;
        float o3 = (v.w - mean) * rstd * g.w + b.w;
        dst[i * 2 + 0] = pack_bf16x2(o0, o1);
        dst[i * 2 + 1] = pack_bf16x2(o2, o3);
    }
}

// ---------------------------------------------------------------------------
// Kernel 5b: convert fc1/fc2/proj weights to bf16.
// ---------------------------------------------------------------------------
__global__ __launch_bounds__(256) void k_cvt(
    const float* __restrict__ w1, const float* __restrict__ w2, const float* __restrict__ wp)
{
    int i = blockIdx.x * 256 + threadIdx.x;
    if (i < 131072)      g_w1b[i] = __float2bfloat16(w1[i]);
    else if (i < 196608) g_w2b[i - 131072] = __float2bfloat16(w2[i - 131072]);
    else if (i < 212992) g_wpb[i - 196608] = __float2bfloat16(wp[i - 196608]);
}

// ---------------------------------------------------------------------------
// Kernel 6: fc1 via mma.sync bf16. Tile M=128, N=128, K=256.
// Grid (1024 M-tiles, 4 N-tiles). Epilogue: +bias, fp32 NCHW into S1+S2.
// ---------------------------------------------------------------------------
__global__ __launch_bounds__(256, 1) void k_fc1_mma(const float* __restrict__ fc1_b_)
{
    extern __shared__ char smc[];
    __nv_bfloat16* Asm = (__nv_bfloat16*)smc;
    __nv_bfloat16* Bsm = Asm + 128 * TSTRIDE;
    uint32_t sA = smem_u32(Asm), sB = smem_u32(Bsm);

    int tid = threadIdx.x, wid = tid >> 5, lane = tid & 31;
    int wm = wid >> 1, wn = wid & 1;
    int mt = blockIdx.x, nt = blockIdx.y;

    const __nv_bfloat16* Asrc = PTR_YN + (size_t)mt * 128 * 256;
    const __nv_bfloat16* Bsrc = g_w1b + (size_t)nt * 128 * 256;
    for (int idx = tid; idx < 4096; idx += 256) {
        int row = idx >> 5, c8 = (idx & 31) << 3;
        *(uint4*)(Asm + row * TSTRIDE + c8) = *(const uint4*)(Asrc + row * 256 + c8);
        *(uint4*)(Bsm + row * TSTRIDE + c8) = *(const uint4*)(Bsrc + row * 256 + c8);
    }
    __syncthreads();

    float c[2][8][4];
    #pragma unroll
    for (int i = 0; i < 2; i++)
        #pragma unroll
        for (int j = 0; j < 8; j++)
            #pragma unroll
            for (int k = 0; k < 4; k++) c[i][j][k] = 0.f;

    mma_tile_bf16<256, TSTRIDE>(sA, sB, lane, wm, wn, c);
    __syncthreads();

    float* T = (float*)smc;   // [128 n][132 token]
    #pragma unroll
    for (int mi = 0; mi < 2; mi++)
        #pragma unroll
        for (int n8 = 0; n8 < 8; n8++) {
            int rt = wm * 32 + mi * 16 + (lane >> 2);
            int cn = wn * 64 + n8 * 8 + (lane & 3) * 2;
            T[cn * 132 + rt]           = c[mi][n8][0];
            T[(cn + 1) * 132 + rt]     = c[mi][n8][1];
            T[cn * 132 + rt + 8]       = c[mi][n8][2];
            T[(cn + 1) * 132 + rt + 8] = c[mi][n8][3];
        }
    __syncthreads();

    int token0 = mt * 128;
    int b = token0 >> 14;
    int hw0 = token0 & 16383;
    int n = tid >> 1, half = tid & 1;
    float bias = fc1_b_[nt * 128 + n];
    float* dst = PTR_FC1 + ((size_t)(b * 512 + nt * 128 + n)) * 16384 + hw0 + half * 64;
    const float* trow = T + n * 132 + half * 64;
    #pragma unroll
    for (int u = 0; u < 16; u++) {
        float4 o = make_float4(trow[u * 4 + 0] + bias, trow[u * 4 + 1] + bias,
                               trow[u * 4 + 2] + bias, trow[u * 4 + 3] + bias);
        *(float4*)(dst + u * 4) = o;
    }
}

// ---------------------------------------------------------------------------
// Kernel 7: depthwise 3x3 conv + gate (fp32 NCHW, unchanged).
// ---------------------------------------------------------------------------
__global__ __launch_bounds__(256) void k_dwgate(
    const float* __restrict__ dw_w, const float* __restrict__ dw_b)
{
    __shared__ float in0[6][130];
    __shared__ float in1[6][130];
    __shared__ float wsm[2][9];
    __shared__ float bsm[2];

    int y0 = blockIdx.x * 4;
    int c  = blockIdx.y;
    int b  = blockIdx.z;
    int tid = threadIdx.x;

    if (tid < 18) { int ch = tid / 9, k = tid - ch * 9; wsm[ch][k] = dw_w[(size_t)(c + ch * 256) * 9 + k]; }
    if (tid < 2) bsm[tid] = dw_b[c + tid * 256];

    for (int e = tid; e < 2 * 6 * 130; e += 256) {
        int ch = e / 780;
        int rem = e - ch * 780;
        int rr = rem / 130;
        int cc = rem - rr * 130;
        int gy = y0 - 1 + rr, gx = cc - 1;
        float v = 0.f;
        if (gy >= 0 && gy < 128 && gx >= 0 && gx < 128)
            v = PTR_FC1[(size_t)(b * 512 + c + ch * 256) * 16384 + gy * 128 + gx];
        if (ch) in1[rr][cc] = v; else in0[rr][cc] = v;
    }
    __syncthreads();

    #pragma unroll
    for (int k = 0; k < 2; k++) {
        int o = tid + k * 256;
        int yy = o >> 7, xx = o & 127;
        float c0 = bsm[0], c1 = bsm[1];
        #pragma unroll
        for (int ky = 0; ky < 3; ky++)
            #pragma unroll
            for (int kx = 0; kx < 3; kx++) {
                c0 += wsm[0][ky * 3 + kx] * in0[yy + ky][xx + kx];
                c1 += wsm[1][ky * 3 + kx] * in1[yy + ky][xx + kx];
            }
        PTR_GATE[(size_t)(b * 256 + c) * 16384 + (y0 + yy) * 128 + xx] = c0 * c1;
    }
}

// ---------------------------------------------------------------------------
// Kernel 8: gate NCHW fp32 -> token-major bf16 (gate_t in S1).
// ---------------------------------------------------------------------------
__global__ __launch_bounds__(256) void k_tr()
{
    __shared__ float t[32][33];
    int hw0 = blockIdx.x * 32, c0 = blockIdx.y * 32, b = blockIdx.z;
    int tx = threadIdx.x & 31, ty = threadIdx.x >> 5;
    #pragma unroll
    for (int i = 0; i < 4; i++) {
        int c = c0 + ty + i * 8;
        t[ty + i * 8][tx] = PTR_GATE[((size_t)(b * 256 + c)) * 16384 + hw0 + tx];
    }
    __syncthreads();
    #pragma unroll
    for (int i = 0; i < 4; i++) {
        int row = ty + i * 8;
        PTR_GT[((size_t)(b * 16384 + hw0 + row)) * 256 + c0 + tx] = __float2bfloat16(t[tx][row]);
    }
}

// ---------------------------------------------------------------------------
// Kernel 9: fc2 via mma.sync bf16. Tile M=128, N=128, K=256. Grid (1024, 2).
// Epilogue: +bias +residual(Y) -> d_out (token-major).
// ---------------------------------------------------------------------------
__global__ __launch_bounds__(256, 1) void k_fc2_mma(
    const float* __restrict__ fc2_b_, float* __restrict__ out)
{
    extern __shared__ char smc[];
    __nv_bfloat16* Asm = (__nv_bfloat16*)smc;
    __nv_bfloat16* Bsm = Asm + 128 * TSTRIDE;
    uint32_t sA = smem_u32(Asm), sB = smem_u32(Bsm);

    int tid = threadIdx.x, wid = tid >> 5, lane = tid & 31;
    int wm = wid >> 1, wn = wid & 1;
    int mt = blockIdx.x, nt = blockIdx.y;

    const __nv_bfloat16* Asrc = PTR_GT + (size_t)mt * 128 * 256;
    const __nv_bfloat16* Bsrc = g_w2b + (size_t)nt * 128 * 256;
    for (int idx = tid; idx < 4096; idx += 256) {
        int row = idx >> 5, c8 = (idx & 31) << 3;
        *(uint4*)(Asm + row * TSTRIDE + c8) = *(const uint4*)(Asrc + row * 256 + c8);
        *(uint4*)(Bsm + row * TSTRIDE + c8) = *(const uint4*)(Bsrc + row * 256 + c8);
    }
    __syncthreads();

    float c[2][8][4];
    #pragma unroll
    for (int i = 0; i < 2; i++)
        #pragma unroll
        for (int j = 0; j < 8; j++)
            #pragma unroll
            for (int k = 0; k < 4; k++) c[i][j][k] = 0.f;

    mma_tile_bf16<256, TSTRIDE>(sA, sB, lane, wm, wn, c);
    __syncthreads();

    float* T = (float*)smc;   // [128 token][132 n]
    #pragma unroll
    for (int mi = 0; mi < 2; mi++)
        #pragma unroll
        for (int n8 = 0; n8 < 8; n8++) {
            int rt = wm * 32 + mi * 16 + (lane >> 2);
            int cn = wn * 64 + n8 * 8 + (lane & 3) * 2;
            T[rt * 132 + cn]           = c[mi][n8][0];
            T[rt * 132 + cn + 1]       = c[mi][n8][1];
            T[(rt + 8) * 132 + cn]     = c[mi][n8][2];
            T[(rt + 8) * 132 + cn + 1] = c[mi][n8][3];
        }
    __syncthreads();

    size_t token0 = (size_t)mt * 128;
    int m = tid >> 1, half = tid & 1;
    int n0 = nt * 128 + half * 64;
    size_t base = (token0 + m) * 256 + n0;
    const float* trow = T + m * 132 + half * 64;
    #pragma unroll
    for (int u = 0; u < 16; u++) {
        float4 y = *(const float4*)(PTR_Y + base + u * 4);
        float4 o;
        o.x = trow[u * 4 + 0] + fc2_b_[n0 + u * 4 + 0] + y.x;
        o.y = trow[u * 4 + 1] + fc2_b_[n0 + u * 4 + 1] + y.y;
        o.z = trow[u * 4 + 2] + fc2_b_[n0 + u * 4 + 2] + y.z;
        o.w = trow[u * 4 + 3] + fc2_b_[n0 + u * 4 + 3] + y.w;
        *(float4*)(out + base + u * 4) = o;
    }
}

// ---------------------------------------------------------------------------
extern "C" void kernel_launch(void* const* d_in, const int* in_sizes, int n_in,
                              void* d_out, int out_size)
{
    const float* x      = (const float*)d_in[0];
    const float* n1g    = (const float*)d_in[1];
    const float* n1b    = (const float*)d_in[2];
    const float* qkv_w  = (const float*)d_in[3];
    const float* qkv_b  = (const float*)d_in[4];
    const float* proj_w = (const float*)d_in[5];
    const float* proj_b = (const float*)d_in[6];
    const float* n2g    = (const float*)d_in[7];
    const float* n2b    = (const float*)d_in[8];
    const float* fc1_w  = (const float*)d_in[9];
    const float* fc1_b  = (const float*)d_in[10];
    const float* dw_w   = (const float*)d_in[11];
    const float* dw_b   = (const float*)d_in[12];
    const float* fc2_w  = (const float*)d_in[13];
    const float* fc2_b  = (const float*)d_in[14];
    float* out = (float*)d_out;

    cudaFuncSetAttribute(k_qkv_mma,  cudaFuncAttributeMaxDynamicSharedMemorySize, 139264);
    cudaFuncSetAttribute(k_proj_mma, cudaFuncAttributeMaxDynamicSharedMemorySize, 135168);
    cudaFuncSetAttribute(k_fc1_mma,  cudaFuncAttributeMaxDynamicSharedMemorySize, 135168);
    cudaFuncSetAttribute(k_fc2_mma,  cudaFuncAttributeMaxDynamicSharedMemorySize, 135168);

    k_cvt<<<832, 256>>>(fc1_w, fc2_w, proj_w);
    k_qkv_mma<<<2048, 256, 139264>>>(x, n1g, n1b, qkv_w, qkv_b);
    k_grad<<<dim3(2048, 2), 256>>>();
    k_attn<<<2048, 512>>>();
    k_proj_mma<<<2048, 256, 135168>>>(x, proj_b);
    k_ln2<<<2048, 256>>>(n2g, n2b);
    k_fc1_mma<<<dim3(1024, 4), 256, 135168>>>(fc1_b);
    k_dwgate<<<dim3(32, 256, 8), 256>>>(dw_w, dw_b);
    k_tr<<<dim3(512, 8, 8), 256>>>();
    k_fc2_mma<<<dim3(1024, 2), 256, 135168>>>(fc2_b, out);
}